// round 12
// baseline (speedup 1.0000x reference)
#include <cuda_runtime.h>
#include <cuda_fp16.h>
#include <stdint.h>

#define Bn  4
#define Ln  2048
#define Dn  1024
#define Hn  16
#define KVn 4
#define HDn 64
#define NROWS (Bn*Ln)          // 8192
#define QKVW  1536             // 1024 + 256 + 256
#define LOG2E 1.44269504088896341f

// ---------------- scratch (device globals; no allocations allowed) ----------
__device__ __half g_xh   [(size_t)NROWS*1024];   // x fp16 [8192][1024]
__device__ __half g_atth [(size_t)NROWS*1024];   // att fp16 [8192][1024]
__device__ __half g_wqkvs[(size_t)QKVW*1024];    // [wq|wk|wv]^T fp16 [1536][1024]
__device__ __half g_wos  [(size_t)1024*1024];    // wo^T fp16 [1024][1024]

// attention operands, fp16, head-major (q pre-scaled by 0.125*log2e)
__device__ __half g_qh[(size_t)Bn*Hn*Ln*HDn];
__device__ __half g_kh[(size_t)Bn*KVn*Ln*HDn];
__device__ __half g_vh[(size_t)Bn*KVn*Ln*HDn];

// ---------------- PTX helpers ----------------------------------------------
__device__ __forceinline__ uint32_t smem_u32(const void* p) {
    uint32_t a;
    asm("{ .reg .u64 t; cvta.to.shared.u64 t, %1; cvt.u32.u64 %0, t; }"
        : "=r"(a) : "l"(p));
    return a;
}
#define SWZ(x) ((x) ^ (((x) >> 3) & 0x70))

__device__ __forceinline__ void cp_async16(uint32_t s, const void* g) {
    asm volatile("cp.async.cg.shared.global [%0], [%1], 16;" :: "r"(s), "l"(g));
}
#define CP_COMMIT() asm volatile("cp.async.commit_group;" ::: "memory")
#define CP_WAIT(n)  asm volatile("cp.async.wait_group %0;" :: "n"(n) : "memory")

__device__ __forceinline__ void ldsm_x4(uint32_t* r, uint32_t addr) {
    asm volatile("ldmatrix.sync.aligned.m8n8.x4.shared.b16 {%0,%1,%2,%3}, [%4];"
        : "=r"(r[0]), "=r"(r[1]), "=r"(r[2]), "=r"(r[3]) : "r"(addr));
}
__device__ __forceinline__ void ldsm_x4_t(uint32_t* r, uint32_t addr) {
    asm volatile("ldmatrix.sync.aligned.m8n8.x4.trans.shared.b16 {%0,%1,%2,%3}, [%4];"
        : "=r"(r[0]), "=r"(r[1]), "=r"(r[2]), "=r"(r[3]) : "r"(addr));
}

__device__ __forceinline__ void mma16816(float* c, const uint32_t* a,
                                         uint32_t b0, uint32_t b1) {
    asm volatile(
        "mma.sync.aligned.m16n8k16.row.col.f32.f16.f16.f32 "
        "{%0,%1,%2,%3}, {%4,%5,%6,%7}, {%8,%9}, {%0,%1,%2,%3};"
        : "+f"(c[0]), "+f"(c[1]), "+f"(c[2]), "+f"(c[3])
        : "r"(a[0]), "r"(a[1]), "r"(a[2]), "r"(a[3]), "r"(b0), "r"(b1));
}

__device__ __forceinline__ uint32_t pack_h2(float lo, float hi) {
    __half2 t = __floats2half2_rn(lo, hi);
    return *(uint32_t*)&t;
}

__device__ __forceinline__ float ex2(float x) {       // force MUFU ex2.approx
    float r;
    asm("ex2.approx.ftz.f32 %0, %1;" : "=f"(r) : "f"(x));
    return r;
}

// ---------------- fused fp32 -> fp16 conversions (single launch) ------------
#define NXA (NROWS * 512)                   // x pairs
#define NWQ (QKVW * 1024)                   // wqkv elems
#define NWO (1024 * 1024)                   // wo elems
#define NCVT (NXA + NWQ + NWO)

__global__ void cvt_all(const float* __restrict__ x,
                        const float* __restrict__ wq, const float* __restrict__ wk,
                        const float* __restrict__ wv, const float* __restrict__ wo)
{
    int i = blockIdx.x * 256 + threadIdx.x;
    if (i < NXA) {
        float2 v = *(const float2*)(x + (size_t)i * 2);
        *(__half2*)(g_xh + (size_t)i * 2) = __floats2half2_rn(v.x, v.y);
    } else if (i < NXA + NWQ) {
        int j = i - NXA;
        int n = j >> 10, k = j & 1023;
        float v;
        if (n < 1024)      v = __ldg(wq + (size_t)k * 1024 + n);
        else if (n < 1280) v = __ldg(wk + (size_t)k * 256 + (n - 1024));
        else               v = __ldg(wv + (size_t)k * 256 + (n - 1280));
        g_wqkvs[(size_t)n * 1024 + k] = __float2half_rn(v);
    } else if (i < NCVT) {
        int j = i - NXA - NWQ;
        int n = j >> 10, k = j & 1023;
        g_wos[(size_t)n * 1024 + k] = __float2half_rn(__ldg(wo + (size_t)k * 1024 + n));
    }
}

// ---------------- HMMA fp16 GEMM: C[128x128] tiles, 8 warps (64x32 each) ----
// 2 CTAs/SM.  mode 0: fp32 C store (WO).  mode 1: RoPE + scatter (QKV).
#define GSTAGES 3
#define NCHUNK 16                    // 1024 / 64
#define STAGE_BYTES 32768            // A 16KB + B 16KB
#define GEMM_SMEM (GSTAGES * STAGE_BYTES)

__global__ __launch_bounds__(256, 2) void gemm_fp16(
    const __half* __restrict__ A, const __half* __restrict__ Bm,
    float* __restrict__ C, int ldc,
    const float* __restrict__ fc, const float* __restrict__ fs, int mode)
{
    extern __shared__ char smraw[];
    uint32_t stg = smem_u32(smraw);
    const int tid  = threadIdx.x;
    const int lane = tid & 31;
    const int w    = tid >> 5;
    const int wm   = w & 1;          // 2 warps along M (64 rows each)
    const int wn   = w >> 1;         // 4 warps along N (32 cols each)
    const int m0 = blockIdx.y * 128, n0 = blockIdx.x * 128;

    const int fr  = lane & 7;
    const int fmi = lane >> 3;
    const int frow = ((fmi & 1) << 3) + fr;
    const int fcol = (fmi >> 1) << 3;

    const __half* Ag0 = A  + (size_t)m0 * 1024;
    const __half* Bg0 = Bm + (size_t)n0 * 1024;

#define ISSUE_LOADS(c, slot) do {                                             \
        uint32_t As_ = stg + (slot) * STAGE_BYTES;                            \
        uint32_t Bs_ = As_ + 16384;                                           \
        const __half* Ag = Ag0 + (c) * 64;                                    \
        const __half* Bg = Bg0 + (c) * 64;                                    \
        _Pragma("unroll")                                                     \
        for (int j_ = 0; j_ < 4; j_++) {                                      \
            int op_ = j_ * 256 + tid;                                         \
            int row_ = op_ >> 3, cb_ = op_ & 7;                               \
            uint32_t so_ = SWZ(row_ * 128 + cb_ * 16);                        \
            cp_async16(As_ + so_, Ag + (size_t)row_ * 1024 + cb_ * 8);        \
            cp_async16(Bs_ + so_, Bg + (size_t)row_ * 1024 + cb_ * 8);        \
        }                                                                     \
        CP_COMMIT();                                                          \
    } while (0)

    ISSUE_LOADS(0, 0);
    ISSUE_LOADS(1, 1);

    float acc[4][4][4];
#pragma unroll
    for (int i = 0; i < 4; i++)
#pragma unroll
        for (int j = 0; j < 4; j++)
#pragma unroll
            for (int q = 0; q < 4; q++) acc[i][j][q] = 0.f;

    int slot = 0, nslot = 2;
    for (int c = 0; c < NCHUNK; c++) {
        CP_WAIT(1);
        __syncthreads();
        if (c + 2 < NCHUNK) ISSUE_LOADS(c + 2, nslot); else CP_COMMIT();

        uint32_t As = stg + slot * STAGE_BYTES;
        uint32_t Bs = As + 16384;
#pragma unroll
        for (int ks = 0; ks < 4; ks++) {
            uint32_t a[4][4], bfr[2][4];
#pragma unroll
            for (int mt = 0; mt < 4; mt++) {
                int row = wm * 64 + mt * 16 + frow;
                ldsm_x4(a[mt], As + SWZ(row * 128 + (ks * 16 + fcol) * 2));
            }
#pragma unroll
            for (int nt = 0; nt < 2; nt++) {
                int row = wn * 32 + nt * 16 + frow;
                ldsm_x4(bfr[nt], Bs + SWZ(row * 128 + (ks * 16 + fcol) * 2));
            }
#pragma unroll
            for (int mt = 0; mt < 4; mt++)
#pragma unroll
                for (int nj = 0; nj < 4; nj++)
                    mma16816(acc[mt][nj], a[mt],
                             bfr[nj >> 1][nj & 1], bfr[nj >> 1][(nj & 1) + 2]);
        }
        slot  = (slot  == GSTAGES - 1) ? 0 : slot + 1;
        nslot = (nslot == GSTAGES - 1) ? 0 : nslot + 1;
    }
#undef ISSUE_LOADS

    if (mode == 0) {
        // plain fp32 store (output projection)
#pragma unroll
        for (int mt = 0; mt < 4; mt++) {
            int row = m0 + wm * 64 + mt * 16 + (lane >> 2);
#pragma unroll
            for (int nj = 0; nj < 4; nj++) {
                int col = n0 + wn * 32 + nj * 8 + ((lane & 3) << 1);
                float2 v0 = {acc[mt][nj][0], acc[mt][nj][1]};
                float2 v1 = {acc[mt][nj][2], acc[mt][nj][3]};
                *(float2*)(C + (size_t)row * ldc + col)       = v0;
                *(float2*)(C + (size_t)(row + 8) * ldc + col) = v1;
            }
        }
    } else {
        // fused RoPE + fp16 scatter (QKV projection); q pre-scaled by log2e/8
#pragma unroll
        for (int mt = 0; mt < 4; mt++) {
            int row = m0 + wm * 64 + mt * 16 + (lane >> 2);
#pragma unroll
            for (int nj = 0; nj < 4; nj++) {
                int col = n0 + wn * 32 + nj * 8 + ((lane & 3) << 1);
#pragma unroll
                for (int half = 0; half < 2; half++) {
                    int r = row + half * 8;
                    float v0 = acc[mt][nj][2 * half];
                    float v1 = acc[mt][nj][2 * half + 1];
                    int bb = r >> 11, l = r & (Ln - 1);
                    int d = col & 63, ii = d >> 1;
                    if (col < 1024) {
                        int h = col >> 6;
                        float cc = fc[l * 32 + ii], ss = fs[l * 32 + ii];
                        size_t ob = ((size_t)(bb * Hn + h) * Ln + l) * HDn + d;
                        const float qs = 0.125f * LOG2E;
                        *(__half2*)(g_qh + ob) = __floats2half2_rn(
                            (v0 * cc - v1 * ss) * qs, (v0 * ss + v1 * cc) * qs);
                    } else if (col < 1280) {
                        int kv = (col - 1024) >> 6;
                        float cc = fc[l * 32 + ii], ss = fs[l * 32 + ii];
                        size_t ob = ((size_t)(bb * KVn + kv) * Ln + l) * HDn + d;
                        *(__half2*)(g_kh + ob) =
                            __floats2half2_rn(v0 * cc - v1 * ss, v0 * ss + v1 * cc);
                    } else {
                        int kv = (col - 1280) >> 6;
                        size_t ob = ((size_t)(bb * KVn + kv) * Ln + l) * HDn + d;
                        *(__half2*)(g_vh + ob) = __floats2half2_rn(v0, v1);
                    }
                }
            }
        }
    }
}

// ---------------- HMMA causal flash attention, BM=128, BN=64 ----------------
// 8 warps x 16 q-rows.  Software-pipelined: QK(kt+1) issues BEFORE
// softmax(kt)+PV(kt) so tensor MMAs hide the serial softmax chain.
#define ASTAGES 4
#define ATT_SMEM (16384 + ASTAGES * 16384)   // Q + 4 stages (K 8K + V 8K)

__global__ __launch_bounds__(256, 2) void attn_mma()
{
    extern __shared__ char smraw[];
    uint32_t sb = smem_u32(smraw);
    // heavy tiles (large qt) first: better tail scheduling on triangular work
    const int qt = (gridDim.x - 1) - blockIdx.x;
    const int h = blockIdx.y, b = blockIdx.z;
    const int tid = threadIdx.x, lane = tid & 31, w = tid >> 5;
    const int frow = (((lane >> 3) & 1) << 3) + (lane & 7);
    const int fcol = (lane >> 4) << 3;

    const uint32_t QH = sb;
    const int kvh = h >> 2;
    const __half* qh_g = g_qh + ((size_t)(b * Hn + h) * Ln + qt * 128) * HDn;
    const __half* kh_g = g_kh + (size_t)(b * KVn + kvh) * Ln * HDn;
    const __half* vh_g = g_vh + (size_t)(b * KVn + kvh) * Ln * HDn;

    const int nkt = 2 * (qt + 1);            // always even
    const int r0g = qt * 128 + w * 16 + (lane >> 2);

#define ISSUE_TILE(kt) do {                                                   \
        uint32_t st_ = sb + 16384 + ((kt) & (ASTAGES - 1)) * 16384;           \
        int kb_ = (kt) * 64;                                                  \
        _Pragma("unroll")                                                     \
        for (int j_ = 0; j_ < 2; j_++) {                                      \
            int op_ = j_ * 256 + tid;                                         \
            int row_ = op_ >> 3, ch_ = op_ & 7;                               \
            uint32_t so_ = SWZ(row_ * 128 + ch_ * 16);                        \
            size_t gs_ = (size_t)(kb_ + row_) * HDn + ch_ * 8;                \
            cp_async16(st_ + so_,        kh_g + gs_);                         \
            cp_async16(st_ + 8192 + so_, vh_g + gs_);                         \
        }                                                                     \
        CP_COMMIT();                                                          \
    } while (0)

// S = Qh.Kh for tile (kt): Q frags reloaded from smem (frees registers)
#define QK_INTO(S, kt) do {                                                   \
        uint32_t Ks_ = sb + 16384 + ((kt) & (ASTAGES - 1)) * 16384;           \
        _Pragma("unroll")                                                     \
        for (int n_ = 0; n_ < 8; n_++)                                        \
            _Pragma("unroll")                                                 \
            for (int q_ = 0; q_ < 4; q_++) (S)[n_][q_] = 0.f;                 \
        _Pragma("unroll")                                                     \
        for (int kc_ = 0; kc_ < 4; kc_++) {                                   \
            uint32_t aq_[4];                                                  \
            ldsm_x4(aq_, QH + SWZ((w * 16 + frow) * 128 + (kc_ * 16 + fcol) * 2)); \
            _Pragma("unroll")                                                 \
            for (int kg_ = 0; kg_ < 4; kg_++) {                               \
                uint32_t bk_[4];                                              \
                ldsm_x4(bk_, Ks_ + SWZ((kg_ * 16 + frow) * 128 + (kc_ * 16 + fcol) * 2)); \
                mma16816((S)[2 * kg_],     aq_, bk_[0], bk_[2]);              \
                mma16816((S)[2 * kg_ + 1], aq_, bk_[1], bk_[3]);              \
            }                                                                 \
        }                                                                     \
    } while (0)

// one tile: QK(kt+1) into SN, then mask/softmax/PV on SC (tile kt)
#define TILE_BODY(kt, SC, SN) do {                                            \
        const bool hn_ = (kt) + 1 < nkt;                                      \
        if (hn_) { CP_WAIT(1); } else { CP_WAIT(0); }                         \
        __syncthreads();                                                      \
        if ((kt) + 3 < nkt) ISSUE_TILE((kt) + 3); else CP_COMMIT();           \
        if (hn_) QK_INTO(SN, (kt) + 1);                                       \
        const int kbase_ = (kt) * 64;                                         \
        if (kbase_ + 63 > qt * 128 + w * 16) {                                \
            _Pragma("unroll")                                                 \
            for (int n_ = 0; n_ < 8; n_++) {                                  \
                int c_ = kbase_ + n_ * 8 + ((lane & 3) << 1);                 \
                if (c_     > r0g)     (SC)[n_][0] = -1e30f;                   \
                if (c_ + 1 > r0g)     (SC)[n_][1] = -1e30f;                   \
                if (c_     > r0g + 8) (SC)[n_][2] = -1e30f;                   \
                if (c_ + 1 > r0g + 8) (SC)[n_][3] = -1e30f;                   \
            }                                                                 \
        }                                                                     \
        float tm0_ = -1e30f, tm1_ = -1e30f;                                   \
        _Pragma("unroll")                                                     \
        for (int n_ = 0; n_ < 8; n_++) {                                      \
            tm0_ = fmaxf(tm0_, fmaxf((SC)[n_][0], (SC)[n_][1]));              \
            tm1_ = fmaxf(tm1_, fmaxf((SC)[n_][2], (SC)[n_][3]));              \
        }                                                                     \
        tm0_ = fmaxf(tm0_, __shfl_xor_sync(0xffffffffu, tm0_, 1));            \
        tm0_ = fmaxf(tm0_, __shfl_xor_sync(0xffffffffu, tm0_, 2));            \
        tm1_ = fmaxf(tm1_, __shfl_xor_sync(0xffffffffu, tm1_, 1));            \
        tm1_ = fmaxf(tm1_, __shfl_xor_sync(0xffffffffu, tm1_, 2));            \
        float mn0_ = fmaxf(m0, tm0_), mn1_ = fmaxf(m1, tm1_);                 \
        float al0_ = ex2(m0 - mn0_), al1_ = ex2(m1 - mn1_);                   \
        m0 = mn0_; m1 = mn1_;                                                 \
        float ps0_ = 0.f, ps1_ = 0.f;                                         \
        _Pragma("unroll")                                                     \
        for (int n_ = 0; n_ < 8; n_++) {                                      \
            (SC)[n_][0] = ex2((SC)[n_][0] - m0);                              \
            (SC)[n_][1] = ex2((SC)[n_][1] - m0);                              \
            (SC)[n_][2] = ex2((SC)[n_][2] - m1);                              \
            (SC)[n_][3] = ex2((SC)[n_][3] - m1);                              \
            ps0_ += (SC)[n_][0] + (SC)[n_][1];                                \
            ps1_ += (SC)[n_][2] + (SC)[n_][3];                                \
        }                                                                     \
        l0 = l0 * al0_ + ps0_;                                                \
        l1 = l1 * al1_ + ps1_;                                                \
        _Pragma("unroll")                                                     \
        for (int n_ = 0; n_ < 8; n_++) {                                      \
            o[n_][0] *= al0_; o[n_][1] *= al0_;                               \
            o[n_][2] *= al1_; o[n_][3] *= al1_;                               \
        }                                                                     \
        uint32_t Vs_ = sb + 16384 + ((kt) & (ASTAGES - 1)) * 16384 + 8192;    \
        _Pragma("unroll")                                                     \
        for (int kg_ = 0; kg_ < 4; kg_++) {                                   \
            uint32_t aph_[4];                                                 \
            aph_[0] = pack_h2((SC)[2 * kg_][0],     (SC)[2 * kg_][1]);        \
            aph_[1] = pack_h2((SC)[2 * kg_][2],     (SC)[2 * kg_][3]);        \
            aph_[2] = pack_h2((SC)[2 * kg_ + 1][0], (SC)[2 * kg_ + 1][1]);    \
            aph_[3] = pack_h2((SC)[2 * kg_ + 1][2], (SC)[2 * kg_ + 1][3]);    \
            _Pragma("unroll")                                                 \
            for (int dg_ = 0; dg_ < 4; dg_++) {                               \
                uint32_t bv_[4];                                              \
                uint32_t so_ = SWZ((kg_ * 16 + frow) * 128 + (dg_ * 16 + fcol) * 2); \
                ldsm_x4_t(bv_, Vs_ + so_);                                    \
                mma16816(o[2 * dg_],     aph_, bv_[0], bv_[1]);               \
                mma16816(o[2 * dg_ + 1], aph_, bv_[2], bv_[3]);               \
            }                                                                 \
        }                                                                     \
    } while (0)

    // prologue: Q + tile0 (group 0), tiles 1,2 (groups 1,2; padded if absent)
#pragma unroll
    for (int j = 0; j < 4; j++) {
        int op = j * 256 + tid;
        int row = op >> 3, ch = op & 7;
        cp_async16(QH + SWZ(row * 128 + ch * 16), qh_g + (size_t)row * HDn + ch * 8);
    }
    ISSUE_TILE(0);
    if (1 < nkt) ISSUE_TILE(1); else CP_COMMIT();
    if (2 < nkt) ISSUE_TILE(2); else CP_COMMIT();
    CP_WAIT(2);
    __syncthreads();

    float o[8][4];
#pragma unroll
    for (int n = 0; n < 8; n++)
#pragma unroll
        for (int q = 0; q < 4; q++) o[n][q] = 0.f;
    float m0 = -1e30f, m1 = -1e30f, l0 = 0.f, l1 = 0.f;

    float sA[8][4], sB[8][4];
    QK_INTO(sA, 0);

    for (int kt = 0; kt < nkt; kt += 2) {
        TILE_BODY(kt,     sA, sB);
        TILE_BODY(kt + 1, sB, sA);
    }
#undef TILE_BODY
#undef QK_INTO
#undef ISSUE_TILE

    // ---- epilogue: write fp16 att rows
    l0 += __shfl_xor_sync(0xffffffffu, l0, 1);
    l0 += __shfl_xor_sync(0xffffffffu, l0, 2);
    l1 += __shfl_xor_sync(0xffffffffu, l1, 1);
    l1 += __shfl_xor_sync(0xffffffffu, l1, 2);
    float inv0 = 1.0f / l0, inv1 = 1.0f / l1;

    size_t row0 = (size_t)(b * Ln + qt * 128 + w * 16 + (lane >> 2));
#pragma unroll
    for (int n = 0; n < 8; n++) {
        int col = h * 64 + n * 8 + ((lane & 3) << 1);
#pragma unroll
        for (int half = 0; half < 2; half++) {
            float v0 = o[n][2 * half]     * (half ? inv1 : inv0);
            float v1 = o[n][2 * half + 1] * (half ? inv1 : inv0);
            *(__half2*)(g_atth + (row0 + half * 8) * 1024 + col) =
                __floats2half2_rn(v0, v1);
        }
    }
}

// ---------------- launch ----------------------------------------------------
extern "C" void kernel_launch(void* const* d_in, const int* in_sizes, int n_in,
                              void* d_out, int out_size)
{
    const float* x  = (const float*)d_in[0];
    const float* wq = (const float*)d_in[1];
    const float* wk = (const float*)d_in[2];
    const float* wv = (const float*)d_in[3];
    const float* wo = (const float*)d_in[4];
    const float* fc = (const float*)d_in[5];
    const float* fs = (const float*)d_in[6];
    // d_in[7] = mask: all-true by construction; causal mask applied exactly.
    float* out = (float*)d_out;
    (void)in_sizes; (void)n_in; (void)out_size;

    __half *xh, *atth, *wqkvs, *wos;
    cudaGetSymbolAddress((void**)&xh,    g_xh);
    cudaGetSymbolAddress((void**)&atth,  g_atth);
    cudaGetSymbolAddress((void**)&wqkvs, g_wqkvs);
    cudaGetSymbolAddress((void**)&wos,   g_wos);

    cudaFuncSetAttribute(gemm_fp16, cudaFuncAttributeMaxDynamicSharedMemorySize, GEMM_SMEM);
    cudaFuncSetAttribute(attn_mma, cudaFuncAttributeMaxDynamicSharedMemorySize, ATT_SMEM);

    // fp16 operand prep (one launch)
    cvt_all<<<(NCVT + 255) / 256, 256>>>(x, wq, wk, wv, wo);

    // fused QKV projection + RoPE + scatter (mode 1)
    gemm_fp16<<<dim3(QKVW / 128, 64), 256, GEMM_SMEM>>>(xh, wqkvs, nullptr, 0, fc, fs, 1);

    // causal GQA attention
    attn_mma<<<dim3(Ln / 128, Hn, Bn), 256, ATT_SMEM>>>();

    // output projection (mode 0)
    gemm_fp16<<<dim3(1024 / 128, 64), 256, GEMM_SMEM>>>(atth, wos, out, 1024, fc, fs, 0);
}

// round 13
// speedup vs baseline: 1.0828x; 1.0828x over previous
#include <cuda_runtime.h>
#include <cuda_fp16.h>
#include <stdint.h>

#define Bn  4
#define Ln  2048
#define Dn  1024
#define Hn  16
#define KVn 4
#define HDn 64
#define NROWS (Bn*Ln)          // 8192
#define QKVW  1536             // 1024 + 256 + 256
#define LOG2E 1.44269504088896341f

// ---------------- scratch (device globals; no allocations allowed) ----------
__device__ __half g_xh   [(size_t)NROWS*1024];   // x fp16 [8192][1024]
__device__ __half g_atth [(size_t)NROWS*1024];   // att fp16 [8192][1024]
__device__ __half g_wqkvs[(size_t)QKVW*1024];    // [wq|wk|wv]^T fp16 [1536][1024]
__device__ __half g_wos  [(size_t)1024*1024];    // wo^T fp16 [1024][1024]

// attention operands, fp16, head-major (q pre-scaled by 0.125*log2e)
__device__ __half g_qh[(size_t)Bn*Hn*Ln*HDn];
__device__ __half g_kh[(size_t)Bn*KVn*Ln*HDn];
__device__ __half g_vh[(size_t)Bn*KVn*Ln*HDn];

// ---------------- PTX helpers ----------------------------------------------
__device__ __forceinline__ uint32_t smem_u32(const void* p) {
    uint32_t a;
    asm("{ .reg .u64 t; cvta.to.shared.u64 t, %1; cvt.u32.u64 %0, t; }"
        : "=r"(a) : "l"(p));
    return a;
}
#define SWZ(x) ((x) ^ (((x) >> 3) & 0x70))

__device__ __forceinline__ void cp_async16(uint32_t s, const void* g) {
    asm volatile("cp.async.cg.shared.global [%0], [%1], 16;" :: "r"(s), "l"(g));
}
#define CP_COMMIT() asm volatile("cp.async.commit_group;" ::: "memory")
#define CP_WAIT(n)  asm volatile("cp.async.wait_group %0;" :: "n"(n) : "memory")

__device__ __forceinline__ void ldsm_x4(uint32_t* r, uint32_t addr) {
    asm volatile("ldmatrix.sync.aligned.m8n8.x4.shared.b16 {%0,%1,%2,%3}, [%4];"
        : "=r"(r[0]), "=r"(r[1]), "=r"(r[2]), "=r"(r[3]) : "r"(addr));
}
__device__ __forceinline__ void ldsm_x4_t(uint32_t* r, uint32_t addr) {
    asm volatile("ldmatrix.sync.aligned.m8n8.x4.trans.shared.b16 {%0,%1,%2,%3}, [%4];"
        : "=r"(r[0]), "=r"(r[1]), "=r"(r[2]), "=r"(r[3]) : "r"(addr));
}

__device__ __forceinline__ void mma16816(float* c, const uint32_t* a,
                                         uint32_t b0, uint32_t b1) {
    asm volatile(
        "mma.sync.aligned.m16n8k16.row.col.f32.f16.f16.f32 "
        "{%0,%1,%2,%3}, {%4,%5,%6,%7}, {%8,%9}, {%0,%1,%2,%3};"
        : "+f"(c[0]), "+f"(c[1]), "+f"(c[2]), "+f"(c[3])
        : "r"(a[0]), "r"(a[1]), "r"(a[2]), "r"(a[3]), "r"(b0), "r"(b1));
}

__device__ __forceinline__ uint32_t pack_h2(float lo, float hi) {
    __half2 t = __floats2half2_rn(lo, hi);
    return *(uint32_t*)&t;
}

__device__ __forceinline__ float ex2(float x) {       // force MUFU ex2.approx
    float r;
    asm("ex2.approx.ftz.f32 %0, %1;" : "=f"(r) : "f"(x));
    return r;
}

// ---------------- fused fp32 -> fp16 conversions (single launch) ------------
#define NXA (NROWS * 512)                   // x pairs
#define NWQ (QKVW * 1024)                   // wqkv elems
#define NWO (1024 * 1024)                   // wo elems
#define NCVT (NXA + NWQ + NWO)

__global__ void cvt_all(const float* __restrict__ x,
                        const float* __restrict__ wq, const float* __restrict__ wk,
                        const float* __restrict__ wv, const float* __restrict__ wo)
{
    int i = blockIdx.x * 256 + threadIdx.x;
    if (i < NXA) {
        float2 v = *(const float2*)(x + (size_t)i * 2);
        *(__half2*)(g_xh + (size_t)i * 2) = __floats2half2_rn(v.x, v.y);
    } else if (i < NXA + NWQ) {
        int j = i - NXA;
        int n = j >> 10, k = j & 1023;
        float v;
        if (n < 1024)      v = __ldg(wq + (size_t)k * 1024 + n);
        else if (n < 1280) v = __ldg(wk + (size_t)k * 256 + (n - 1024));
        else               v = __ldg(wv + (size_t)k * 256 + (n - 1280));
        g_wqkvs[(size_t)n * 1024 + k] = __float2half_rn(v);
    } else if (i < NCVT) {
        int j = i - NXA - NWQ;
        int n = j >> 10, k = j & 1023;
        g_wos[(size_t)n * 1024 + k] = __float2half_rn(__ldg(wo + (size_t)k * 1024 + n));
    }
}

// ---------------- HMMA fp16 GEMM: C[128x128] tiles, 8 warps (64x32 each) ----
// 2 CTAs/SM.  mode 0: fp32 C store (WO).  mode 1: RoPE + scatter (QKV).
#define GSTAGES 3
#define NCHUNK 16                    // 1024 / 64
#define STAGE_BYTES 32768            // A 16KB + B 16KB
#define GEMM_SMEM (GSTAGES * STAGE_BYTES)

__global__ __launch_bounds__(256, 2) void gemm_fp16(
    const __half* __restrict__ A, const __half* __restrict__ Bm,
    float* __restrict__ C, int ldc,
    const float* __restrict__ fc, const float* __restrict__ fs, int mode)
{
    extern __shared__ char smraw[];
    uint32_t stg = smem_u32(smraw);
    const int tid  = threadIdx.x;
    const int lane = tid & 31;
    const int w    = tid >> 5;
    const int wm   = w & 1;          // 2 warps along M (64 rows each)
    const int wn   = w >> 1;         // 4 warps along N (32 cols each)
    const int m0 = blockIdx.y * 128, n0 = blockIdx.x * 128;

    const int fr  = lane & 7;
    const int fmi = lane >> 3;
    const int frow = ((fmi & 1) << 3) + fr;
    const int fcol = (fmi >> 1) << 3;

    const __half* Ag0 = A  + (size_t)m0 * 1024;
    const __half* Bg0 = Bm + (size_t)n0 * 1024;

#define ISSUE_LOADS(c, slot) do {                                             \
        uint32_t As_ = stg + (slot) * STAGE_BYTES;                            \
        uint32_t Bs_ = As_ + 16384;                                           \
        const __half* Ag = Ag0 + (c) * 64;                                    \
        const __half* Bg = Bg0 + (c) * 64;                                    \
        _Pragma("unroll")                                                     \
        for (int j_ = 0; j_ < 4; j_++) {                                      \
            int op_ = j_ * 256 + tid;                                         \
            int row_ = op_ >> 3, cb_ = op_ & 7;                               \
            uint32_t so_ = SWZ(row_ * 128 + cb_ * 16);                        \
            cp_async16(As_ + so_, Ag + (size_t)row_ * 1024 + cb_ * 8);        \
            cp_async16(Bs_ + so_, Bg + (size_t)row_ * 1024 + cb_ * 8);        \
        }                                                                     \
        CP_COMMIT();                                                          \
    } while (0)

    ISSUE_LOADS(0, 0);
    ISSUE_LOADS(1, 1);

    float acc[4][4][4];
#pragma unroll
    for (int i = 0; i < 4; i++)
#pragma unroll
        for (int j = 0; j < 4; j++)
#pragma unroll
            for (int q = 0; q < 4; q++) acc[i][j][q] = 0.f;

    int slot = 0, nslot = 2;
    for (int c = 0; c < NCHUNK; c++) {
        CP_WAIT(1);
        __syncthreads();
        if (c + 2 < NCHUNK) ISSUE_LOADS(c + 2, nslot); else CP_COMMIT();

        uint32_t As = stg + slot * STAGE_BYTES;
        uint32_t Bs = As + 16384;
#pragma unroll
        for (int ks = 0; ks < 4; ks++) {
            uint32_t a[4][4], bfr[2][4];
#pragma unroll
            for (int mt = 0; mt < 4; mt++) {
                int row = wm * 64 + mt * 16 + frow;
                ldsm_x4(a[mt], As + SWZ(row * 128 + (ks * 16 + fcol) * 2));
            }
#pragma unroll
            for (int nt = 0; nt < 2; nt++) {
                int row = wn * 32 + nt * 16 + frow;
                ldsm_x4(bfr[nt], Bs + SWZ(row * 128 + (ks * 16 + fcol) * 2));
            }
#pragma unroll
            for (int mt = 0; mt < 4; mt++)
#pragma unroll
                for (int nj = 0; nj < 4; nj++)
                    mma16816(acc[mt][nj], a[mt],
                             bfr[nj >> 1][nj & 1], bfr[nj >> 1][(nj & 1) + 2]);
        }
        slot  = (slot  == GSTAGES - 1) ? 0 : slot + 1;
        nslot = (nslot == GSTAGES - 1) ? 0 : nslot + 1;
    }
#undef ISSUE_LOADS

    if (mode == 0) {
        // plain fp32 store (output projection)
#pragma unroll
        for (int mt = 0; mt < 4; mt++) {
            int row = m0 + wm * 64 + mt * 16 + (lane >> 2);
#pragma unroll
            for (int nj = 0; nj < 4; nj++) {
                int col = n0 + wn * 32 + nj * 8 + ((lane & 3) << 1);
                float2 v0 = {acc[mt][nj][0], acc[mt][nj][1]};
                float2 v1 = {acc[mt][nj][2], acc[mt][nj][3]};
                *(float2*)(C + (size_t)row * ldc + col)       = v0;
                *(float2*)(C + (size_t)(row + 8) * ldc + col) = v1;
            }
        }
    } else {
        // fused RoPE + fp16 scatter (QKV projection); q pre-scaled by log2e/8
#pragma unroll
        for (int mt = 0; mt < 4; mt++) {
            int row = m0 + wm * 64 + mt * 16 + (lane >> 2);
#pragma unroll
            for (int nj = 0; nj < 4; nj++) {
                int col = n0 + wn * 32 + nj * 8 + ((lane & 3) << 1);
#pragma unroll
                for (int half = 0; half < 2; half++) {
                    int r = row + half * 8;
                    float v0 = acc[mt][nj][2 * half];
                    float v1 = acc[mt][nj][2 * half + 1];
                    int bb = r >> 11, l = r & (Ln - 1);
                    int d = col & 63, ii = d >> 1;
                    if (col < 1024) {
                        int h = col >> 6;
                        float cc = fc[l * 32 + ii], ss = fs[l * 32 + ii];
                        size_t ob = ((size_t)(bb * Hn + h) * Ln + l) * HDn + d;
                        const float qs = 0.125f * LOG2E;
                        *(__half2*)(g_qh + ob) = __floats2half2_rn(
                            (v0 * cc - v1 * ss) * qs, (v0 * ss + v1 * cc) * qs);
                    } else if (col < 1280) {
                        int kv = (col - 1024) >> 6;
                        float cc = fc[l * 32 + ii], ss = fs[l * 32 + ii];
                        size_t ob = ((size_t)(bb * KVn + kv) * Ln + l) * HDn + d;
                        *(__half2*)(g_kh + ob) =
                            __floats2half2_rn(v0 * cc - v1 * ss, v0 * ss + v1 * cc);
                    } else {
                        int kv = (col - 1280) >> 6;
                        size_t ob = ((size_t)(bb * KVn + kv) * Ln + l) * HDn + d;
                        *(__half2*)(g_vh + ob) = __floats2half2_rn(v0, v1);
                    }
                }
            }
        }
    }
}

// ---------------- HMMA causal flash attention, BM=128, BN=64 ----------------
// 8 warps x 16 q-rows. S = Qh.Kh (base-2 scaled); O = Ph.Vh.
// 4-stage K/V ring, ONE sync per tile.  (R11 structure + MUFU ex2)
#define ASTAGES 4
#define ATT_SMEM (16384 + ASTAGES * 16384)   // Q + 4 stages (K 8K + V 8K)

__global__ __launch_bounds__(256, 2) void attn_mma()
{
    extern __shared__ char smraw[];
    uint32_t sb = smem_u32(smraw);
    // heavy tiles (large qt) first: better tail scheduling on triangular work
    const int qt = (gridDim.x - 1) - blockIdx.x;
    const int h = blockIdx.y, b = blockIdx.z;
    const int tid = threadIdx.x, lane = tid & 31, w = tid >> 5;
    const int frow = (((lane >> 3) & 1) << 3) + (lane & 7);
    const int fcol = (lane >> 4) << 3;

    const uint32_t QH = sb;
    const int kvh = h >> 2;
    const __half* qh_g = g_qh + ((size_t)(b * Hn + h) * Ln + qt * 128) * HDn;
    const __half* kh_g = g_kh + (size_t)(b * KVn + kvh) * Ln * HDn;
    const __half* vh_g = g_vh + (size_t)(b * KVn + kvh) * Ln * HDn;

    const int nkt = 2 * (qt + 1);

#define ISSUE_TILE(kt) do {                                                   \
        uint32_t st_ = sb + 16384 + ((kt) & (ASTAGES - 1)) * 16384;           \
        int kb_ = (kt) * 64;                                                  \
        _Pragma("unroll")                                                     \
        for (int j_ = 0; j_ < 2; j_++) {                                      \
            int op_ = j_ * 256 + tid;                                         \
            int row_ = op_ >> 3, ch_ = op_ & 7;                               \
            uint32_t so_ = SWZ(row_ * 128 + ch_ * 16);                        \
            size_t gs_ = (size_t)(kb_ + row_) * HDn + ch_ * 8;                \
            cp_async16(st_ + so_,        kh_g + gs_);                         \
            cp_async16(st_ + 8192 + so_, vh_g + gs_);                         \
        }                                                                     \
        CP_COMMIT();                                                          \
    } while (0)

    // prologue: Q folded into group 0; issue 3 tile-groups (pad with empties)
#pragma unroll
    for (int j = 0; j < 4; j++) {
        int op = j * 256 + tid;
        int row = op >> 3, ch = op & 7;
        cp_async16(QH + SWZ(row * 128 + ch * 16), qh_g + (size_t)row * HDn + ch * 8);
    }
    ISSUE_TILE(0);                           // group 0 = Q + tile0
    if (1 < nkt) ISSUE_TILE(1); else CP_COMMIT();
    if (2 < nkt) ISSUE_TILE(2); else CP_COMMIT();

    float o[8][4];
#pragma unroll
    for (int n = 0; n < 8; n++)
#pragma unroll
        for (int q = 0; q < 4; q++) o[n][q] = 0.f;
    float m0 = -1e30f, m1 = -1e30f, l0 = 0.f, l1 = 0.f;
    uint32_t aqh[4][4];

    const int r0g = qt * 128 + w * 16 + (lane >> 2);

    for (int kt = 0; kt < nkt; kt++) {
        CP_WAIT(2);                          // oldest pending (tile kt) resident
        __syncthreads();                     // single CTA barrier per tile
        if (kt + 3 < nkt) ISSUE_TILE(kt + 3); else CP_COMMIT();

        if (kt == 0) {
#pragma unroll
            for (int kc = 0; kc < 4; kc++)
                ldsm_x4(aqh[kc], QH + SWZ((w * 16 + frow) * 128 + (kc * 16 + fcol) * 2));
        }

        uint32_t st = sb + 16384 + (kt & (ASTAGES - 1)) * 16384;
        uint32_t KHs = st, VHs = st + 8192;

        // ---- S = Qh . Kh   (S is in base-2 units: q pre-scaled by log2e/8)
        float s[8][4];
#pragma unroll
        for (int n = 0; n < 8; n++)
#pragma unroll
            for (int q = 0; q < 4; q++) s[n][q] = 0.f;

#pragma unroll
        for (int kc = 0; kc < 4; kc++) {
#pragma unroll
            for (int kg = 0; kg < 4; kg++) {
                uint32_t bk[4];
                ldsm_x4(bk, KHs + SWZ((kg * 16 + frow) * 128 + (kc * 16 + fcol) * 2));
                mma16816(s[2 * kg],     aqh[kc], bk[0], bk[2]);
                mma16816(s[2 * kg + 1], aqh[kc], bk[1], bk[3]);
            }
        }

        // ---- causal mask
        const int kbase = kt * 64;
        if (kbase + 63 > qt * 128 + w * 16) {
#pragma unroll
            for (int n = 0; n < 8; n++) {
                int c = kbase + n * 8 + ((lane & 3) << 1);
                if (c     > r0g)     s[n][0] = -1e30f;
                if (c + 1 > r0g)     s[n][1] = -1e30f;
                if (c     > r0g + 8) s[n][2] = -1e30f;
                if (c + 1 > r0g + 8) s[n][3] = -1e30f;
            }
        }

        // ---- online softmax (base 2, MUFU ex2)
        float tm0 = -1e30f, tm1 = -1e30f;
#pragma unroll
        for (int n = 0; n < 8; n++) {
            tm0 = fmaxf(tm0, fmaxf(s[n][0], s[n][1]));
            tm1 = fmaxf(tm1, fmaxf(s[n][2], s[n][3]));
        }
        tm0 = fmaxf(tm0, __shfl_xor_sync(0xffffffffu, tm0, 1));
        tm0 = fmaxf(tm0, __shfl_xor_sync(0xffffffffu, tm0, 2));
        tm1 = fmaxf(tm1, __shfl_xor_sync(0xffffffffu, tm1, 1));
        tm1 = fmaxf(tm1, __shfl_xor_sync(0xffffffffu, tm1, 2));
        float mn0 = fmaxf(m0, tm0), mn1 = fmaxf(m1, tm1);
        float al0 = ex2(m0 - mn0), al1 = ex2(m1 - mn1);
        m0 = mn0; m1 = mn1;
        float ps0 = 0.f, ps1 = 0.f;
#pragma unroll
        for (int n = 0; n < 8; n++) {
            s[n][0] = ex2(s[n][0] - m0);
            s[n][1] = ex2(s[n][1] - m0);
            s[n][2] = ex2(s[n][2] - m1);
            s[n][3] = ex2(s[n][3] - m1);
            ps0 += s[n][0] + s[n][1];
            ps1 += s[n][2] + s[n][3];
        }
        l0 = l0 * al0 + ps0;
        l1 = l1 * al1 + ps1;
#pragma unroll
        for (int n = 0; n < 8; n++) {
            o[n][0] *= al0; o[n][1] *= al0;
            o[n][2] *= al1; o[n][3] *= al1;
        }

        // ---- O += Ph . Vh  (single fp16 pass)
#pragma unroll
        for (int kg = 0; kg < 4; kg++) {
            uint32_t aph[4];
            aph[0] = pack_h2(s[2 * kg][0],     s[2 * kg][1]);
            aph[1] = pack_h2(s[2 * kg][2],     s[2 * kg][3]);
            aph[2] = pack_h2(s[2 * kg + 1][0], s[2 * kg + 1][1]);
            aph[3] = pack_h2(s[2 * kg + 1][2], s[2 * kg + 1][3]);
#pragma unroll
            for (int dg = 0; dg < 4; dg++) {
                uint32_t bv[4];
                uint32_t so = SWZ((kg * 16 + frow) * 128 + (dg * 16 + fcol) * 2);
                ldsm_x4_t(bv, VHs + so);
                mma16816(o[2 * dg],     aph, bv[0], bv[1]);
                mma16816(o[2 * dg + 1], aph, bv[2], bv[3]);
            }
        }
    }
#undef ISSUE_TILE

    // ---- epilogue: write fp16 att rows
    l0 += __shfl_xor_sync(0xffffffffu, l0, 1);
    l0 += __shfl_xor_sync(0xffffffffu, l0, 2);
    l1 += __shfl_xor_sync(0xffffffffu, l1, 1);
    l1 += __shfl_xor_sync(0xffffffffu, l1, 2);
    float inv0 = 1.0f / l0, inv1 = 1.0f / l1;

    size_t row0 = (size_t)(b * Ln + qt * 128 + w * 16 + (lane >> 2));
#pragma unroll
    for (int n = 0; n < 8; n++) {
        int col = h * 64 + n * 8 + ((lane & 3) << 1);
#pragma unroll
        for (int half = 0; half < 2; half++) {
            float v0 = o[n][2 * half]     * (half ? inv1 : inv0);
            float v1 = o[n][2 * half + 1] * (half ? inv1 : inv0);
            *(__half2*)(g_atth + (row0 + half * 8) * 1024 + col) =
                __floats2half2_rn(v0, v1);
        }
    }
}

// ---------------- launch ----------------------------------------------------
extern "C" void kernel_launch(void* const* d_in, const int* in_sizes, int n_in,
                              void* d_out, int out_size)
{
    const float* x  = (const float*)d_in[0];
    const float* wq = (const float*)d_in[1];
    const float* wk = (const float*)d_in[2];
    const float* wv = (const float*)d_in[3];
    const float* wo = (const float*)d_in[4];
    const float* fc = (const float*)d_in[5];
    const float* fs = (const float*)d_in[6];
    // d_in[7] = mask: all-true by construction; causal mask applied exactly.
    float* out = (float*)d_out;
    (void)in_sizes; (void)n_in; (void)out_size;

    __half *xh, *atth, *wqkvs, *wos;
    cudaGetSymbolAddress((void**)&xh,    g_xh);
    cudaGetSymbolAddress((void**)&atth,  g_atth);
    cudaGetSymbolAddress((void**)&wqkvs, g_wqkvs);
    cudaGetSymbolAddress((void**)&wos,   g_wos);

    cudaFuncSetAttribute(gemm_fp16, cudaFuncAttributeMaxDynamicSharedMemorySize, GEMM_SMEM);
    cudaFuncSetAttribute(attn_mma, cudaFuncAttributeMaxDynamicSharedMemorySize, ATT_SMEM);

    // fp16 operand prep (one launch)
    cvt_all<<<(NCVT + 255) / 256, 256>>>(x, wq, wk, wv, wo);

    // fused QKV projection + RoPE + scatter (mode 1)
    gemm_fp16<<<dim3(QKVW / 128, 64), 256, GEMM_SMEM>>>(xh, wqkvs, nullptr, 0, fc, fs, 1);

    // causal GQA attention
    attn_mma<<<dim3(Ln / 128, Hn, Bn), 256, ATT_SMEM>>>();

    // output projection (mode 0)
    gemm_fp16<<<dim3(1024 / 128, 64), 256, GEMM_SMEM>>>(atth, wos, out, 1024, fc, fs, 0);
}

// round 14
// speedup vs baseline: 1.0831x; 1.0003x over previous
#include <cuda_runtime.h>
#include <cuda_fp16.h>
#include <stdint.h>

#define Bn  4
#define Ln  2048
#define Dn  1024
#define Hn  16
#define KVn 4
#define HDn 64
#define NROWS (Bn*Ln)          // 8192
#define QKVW  1536             // 1024 + 256 + 256
#define LOG2E 1.44269504088896341f

// ---------------- scratch (device globals; no allocations allowed) ----------
__device__ __half g_xh   [(size_t)NROWS*1024];   // x fp16 [8192][1024]
__device__ __half g_atth [(size_t)NROWS*1024];   // att fp16 [8192][1024]
__device__ __half g_wqkvs[(size_t)QKVW*1024];    // [wq|wk|wv]^T fp16 [1536][1024]
__device__ __half g_wos  [(size_t)1024*1024];    // wo^T fp16 [1024][1024]

// attention operands, fp16, head-major (q pre-scaled by 0.125*log2e)
__device__ __half g_qh[(size_t)Bn*Hn*Ln*HDn];
__device__ __half g_kh[(size_t)Bn*KVn*Ln*HDn];
__device__ __half g_vh[(size_t)Bn*KVn*Ln*HDn];

// ---------------- PTX helpers ----------------------------------------------
__device__ __forceinline__ uint32_t smem_u32(const void* p) {
    uint32_t a;
    asm("{ .reg .u64 t; cvta.to.shared.u64 t, %1; cvt.u32.u64 %0, t; }"
        : "=r"(a) : "l"(p));
    return a;
}
#define SWZ(x) ((x) ^ (((x) >> 3) & 0x70))

__device__ __forceinline__ void cp_async16(uint32_t s, const void* g) {
    asm volatile("cp.async.cg.shared.global [%0], [%1], 16;" :: "r"(s), "l"(g));
}
#define CP_COMMIT() asm volatile("cp.async.commit_group;" ::: "memory")
#define CP_WAIT(n)  asm volatile("cp.async.wait_group %0;" :: "n"(n) : "memory")

__device__ __forceinline__ void ldsm_x4(uint32_t* r, uint32_t addr) {
    asm volatile("ldmatrix.sync.aligned.m8n8.x4.shared.b16 {%0,%1,%2,%3}, [%4];"
        : "=r"(r[0]), "=r"(r[1]), "=r"(r[2]), "=r"(r[3]) : "r"(addr));
}
__device__ __forceinline__ void ldsm_x4_t(uint32_t* r, uint32_t addr) {
    asm volatile("ldmatrix.sync.aligned.m8n8.x4.trans.shared.b16 {%0,%1,%2,%3}, [%4];"
        : "=r"(r[0]), "=r"(r[1]), "=r"(r[2]), "=r"(r[3]) : "r"(addr));
}

__device__ __forceinline__ void mma16816(float* c, const uint32_t* a,
                                         uint32_t b0, uint32_t b1) {
    asm volatile(
        "mma.sync.aligned.m16n8k16.row.col.f32.f16.f16.f32 "
        "{%0,%1,%2,%3}, {%4,%5,%6,%7}, {%8,%9}, {%0,%1,%2,%3};"
        : "+f"(c[0]), "+f"(c[1]), "+f"(c[2]), "+f"(c[3])
        : "r"(a[0]), "r"(a[1]), "r"(a[2]), "r"(a[3]), "r"(b0), "r"(b1));
}

__device__ __forceinline__ uint32_t pack_h2(float lo, float hi) {
    __half2 t = __floats2half2_rn(lo, hi);
    return *(uint32_t*)&t;
}

__device__ __forceinline__ float ex2(float x) {       // force MUFU ex2.approx
    float r;
    asm("ex2.approx.ftz.f32 %0, %1;" : "=f"(r) : "f"(x));
    return r;
}

// ---------------- fused fp32 -> fp16 conversions (single launch) ------------
#define NXA (NROWS * 512)                   // x pairs
#define NWQ (QKVW * 1024)                   // wqkv elems
#define NWO (1024 * 1024)                   // wo elems
#define NCVT (NXA + NWQ + NWO)

__global__ void cvt_all(const float* __restrict__ x,
                        const float* __restrict__ wq, const float* __restrict__ wk,
                        const float* __restrict__ wv, const float* __restrict__ wo)
{
    int i = blockIdx.x * 256 + threadIdx.x;
    if (i < NXA) {
        float2 v = *(const float2*)(x + (size_t)i * 2);
        *(__half2*)(g_xh + (size_t)i * 2) = __floats2half2_rn(v.x, v.y);
    } else if (i < NXA + NWQ) {
        int j = i - NXA;
        int n = j >> 10, k = j & 1023;
        float v;
        if (n < 1024)      v = __ldg(wq + (size_t)k * 1024 + n);
        else if (n < 1280) v = __ldg(wk + (size_t)k * 256 + (n - 1024));
        else               v = __ldg(wv + (size_t)k * 256 + (n - 1280));
        g_wqkvs[(size_t)n * 1024 + k] = __float2half_rn(v);
    } else if (i < NCVT) {
        int j = i - NXA - NWQ;
        int n = j >> 10, k = j & 1023;
        g_wos[(size_t)n * 1024 + k] = __float2half_rn(__ldg(wo + (size_t)k * 1024 + n));
    }
}

// ---------------- HMMA fp16 GEMM: C[128x128] tiles, 8 warps (64x32 each) ----
// 2 CTAs/SM.  mode 0: fp32 C store (WO).  mode 1: RoPE + scatter (QKV).
#define GSTAGES 3
#define NCHUNK 16                    // 1024 / 64
#define STAGE_BYTES 32768            // A 16KB + B 16KB
#define GEMM_SMEM (GSTAGES * STAGE_BYTES)

__global__ __launch_bounds__(256, 2) void gemm_fp16(
    const __half* __restrict__ A, const __half* __restrict__ Bm,
    float* __restrict__ C, int ldc,
    const float* __restrict__ fc, const float* __restrict__ fs, int mode)
{
    extern __shared__ char smraw[];
    uint32_t stg = smem_u32(smraw);
    const int tid  = threadIdx.x;
    const int lane = tid & 31;
    const int w    = tid >> 5;
    const int wm   = w & 1;          // 2 warps along M (64 rows each)
    const int wn   = w >> 1;         // 4 warps along N (32 cols each)
    const int m0 = blockIdx.y * 128, n0 = blockIdx.x * 128;

    const int fr  = lane & 7;
    const int fmi = lane >> 3;
    const int frow = ((fmi & 1) << 3) + fr;
    const int fcol = (fmi >> 1) << 3;

    const __half* Ag0 = A  + (size_t)m0 * 1024;
    const __half* Bg0 = Bm + (size_t)n0 * 1024;

#define ISSUE_LOADS(c, slot) do {                                             \
        uint32_t As_ = stg + (slot) * STAGE_BYTES;                            \
        uint32_t Bs_ = As_ + 16384;                                           \
        const __half* Ag = Ag0 + (c) * 64;                                    \
        const __half* Bg = Bg0 + (c) * 64;                                    \
        _Pragma("unroll")                                                     \
        for (int j_ = 0; j_ < 4; j_++) {                                      \
            int op_ = j_ * 256 + tid;                                         \
            int row_ = op_ >> 3, cb_ = op_ & 7;                               \
            uint32_t so_ = SWZ(row_ * 128 + cb_ * 16);                        \
            cp_async16(As_ + so_, Ag + (size_t)row_ * 1024 + cb_ * 8);        \
            cp_async16(Bs_ + so_, Bg + (size_t)row_ * 1024 + cb_ * 8);        \
        }                                                                     \
        CP_COMMIT();                                                          \
    } while (0)

    ISSUE_LOADS(0, 0);
    ISSUE_LOADS(1, 1);

    float acc[4][4][4];
#pragma unroll
    for (int i = 0; i < 4; i++)
#pragma unroll
        for (int j = 0; j < 4; j++)
#pragma unroll
            for (int q = 0; q < 4; q++) acc[i][j][q] = 0.f;

    int slot = 0, nslot = 2;
    for (int c = 0; c < NCHUNK; c++) {
        CP_WAIT(1);
        __syncthreads();
        if (c + 2 < NCHUNK) ISSUE_LOADS(c + 2, nslot); else CP_COMMIT();

        uint32_t As = stg + slot * STAGE_BYTES;
        uint32_t Bs = As + 16384;
#pragma unroll
        for (int ks = 0; ks < 4; ks++) {
            uint32_t a[4][4], bfr[2][4];
#pragma unroll
            for (int mt = 0; mt < 4; mt++) {
                int row = wm * 64 + mt * 16 + frow;
                ldsm_x4(a[mt], As + SWZ(row * 128 + (ks * 16 + fcol) * 2));
            }
#pragma unroll
            for (int nt = 0; nt < 2; nt++) {
                int row = wn * 32 + nt * 16 + frow;
                ldsm_x4(bfr[nt], Bs + SWZ(row * 128 + (ks * 16 + fcol) * 2));
            }
#pragma unroll
            for (int mt = 0; mt < 4; mt++)
#pragma unroll
                for (int nj = 0; nj < 4; nj++)
                    mma16816(acc[mt][nj], a[mt],
                             bfr[nj >> 1][nj & 1], bfr[nj >> 1][(nj & 1) + 2]);
        }
        slot  = (slot  == GSTAGES - 1) ? 0 : slot + 1;
        nslot = (nslot == GSTAGES - 1) ? 0 : nslot + 1;
    }
#undef ISSUE_LOADS

    if (mode == 0) {
        // plain fp32 store (output projection)
#pragma unroll
        for (int mt = 0; mt < 4; mt++) {
            int row = m0 + wm * 64 + mt * 16 + (lane >> 2);
#pragma unroll
            for (int nj = 0; nj < 4; nj++) {
                int col = n0 + wn * 32 + nj * 8 + ((lane & 3) << 1);
                float2 v0 = {acc[mt][nj][0], acc[mt][nj][1]};
                float2 v1 = {acc[mt][nj][2], acc[mt][nj][3]};
                *(float2*)(C + (size_t)row * ldc + col)       = v0;
                *(float2*)(C + (size_t)(row + 8) * ldc + col) = v1;
            }
        }
    } else {
        // fused RoPE + fp16 scatter (QKV projection); q pre-scaled by log2e/8
#pragma unroll
        for (int mt = 0; mt < 4; mt++) {
            int row = m0 + wm * 64 + mt * 16 + (lane >> 2);
#pragma unroll
            for (int nj = 0; nj < 4; nj++) {
                int col = n0 + wn * 32 + nj * 8 + ((lane & 3) << 1);
#pragma unroll
                for (int half = 0; half < 2; half++) {
                    int r = row + half * 8;
                    float v0 = acc[mt][nj][2 * half];
                    float v1 = acc[mt][nj][2 * half + 1];
                    int bb = r >> 11, l = r & (Ln - 1);
                    int d = col & 63, ii = d >> 1;
                    if (col < 1024) {
                        int h = col >> 6;
                        float cc = fc[l * 32 + ii], ss = fs[l * 32 + ii];
                        size_t ob = ((size_t)(bb * Hn + h) * Ln + l) * HDn + d;
                        const float qs = 0.125f * LOG2E;
                        *(__half2*)(g_qh + ob) = __floats2half2_rn(
                            (v0 * cc - v1 * ss) * qs, (v0 * ss + v1 * cc) * qs);
                    } else if (col < 1280) {
                        int kv = (col - 1024) >> 6;
                        float cc = fc[l * 32 + ii], ss = fs[l * 32 + ii];
                        size_t ob = ((size_t)(bb * KVn + kv) * Ln + l) * HDn + d;
                        *(__half2*)(g_kh + ob) =
                            __floats2half2_rn(v0 * cc - v1 * ss, v0 * ss + v1 * cc);
                    } else {
                        int kv = (col - 1280) >> 6;
                        size_t ob = ((size_t)(bb * KVn + kv) * Ln + l) * HDn + d;
                        *(__half2*)(g_vh + ob) = __floats2half2_rn(v0, v1);
                    }
                }
            }
        }
    }
}

// ---------------- HMMA causal flash attention, BM=128, BN=64 ----------------
// 8 warps x 16 q-rows. S = Qh.Kh (base-2 scaled); O = Ph.Vh.
// 4-stage K/V ring, ONE sync per tile.  (R11 structure + MUFU ex2)
#define ASTAGES 4
#define ATT_SMEM (16384 + ASTAGES * 16384)   // Q + 4 stages (K 8K + V 8K)

__global__ __launch_bounds__(256, 2) void attn_mma()
{
    extern __shared__ char smraw[];
    uint32_t sb = smem_u32(smraw);
    // heavy tiles (large qt) first: better tail scheduling on triangular work
    const int qt = (gridDim.x - 1) - blockIdx.x;
    const int h = blockIdx.y, b = blockIdx.z;
    const int tid = threadIdx.x, lane = tid & 31, w = tid >> 5;
    const int frow = (((lane >> 3) & 1) << 3) + (lane & 7);
    const int fcol = (lane >> 4) << 3;

    const uint32_t QH = sb;
    const int kvh = h >> 2;
    const __half* qh_g = g_qh + ((size_t)(b * Hn + h) * Ln + qt * 128) * HDn;
    const __half* kh_g = g_kh + (size_t)(b * KVn + kvh) * Ln * HDn;
    const __half* vh_g = g_vh + (size_t)(b * KVn + kvh) * Ln * HDn;

    const int nkt = 2 * (qt + 1);

#define ISSUE_TILE(kt) do {                                                   \
        uint32_t st_ = sb + 16384 + ((kt) & (ASTAGES - 1)) * 16384;           \
        int kb_ = (kt) * 64;                                                  \
        _Pragma("unroll")                                                     \
        for (int j_ = 0; j_ < 2; j_++) {                                      \
            int op_ = j_ * 256 + tid;                                         \
            int row_ = op_ >> 3, ch_ = op_ & 7;                               \
            uint32_t so_ = SWZ(row_ * 128 + ch_ * 16);                        \
            size_t gs_ = (size_t)(kb_ + row_) * HDn + ch_ * 8;                \
            cp_async16(st_ + so_,        kh_g + gs_);                         \
            cp_async16(st_ + 8192 + so_, vh_g + gs_);                         \
        }                                                                     \
        CP_COMMIT();                                                          \
    } while (0)

    // prologue: Q folded into group 0; issue 3 tile-groups (pad with empties)
#pragma unroll
    for (int j = 0; j < 4; j++) {
        int op = j * 256 + tid;
        int row = op >> 3, ch = op & 7;
        cp_async16(QH + SWZ(row * 128 + ch * 16), qh_g + (size_t)row * HDn + ch * 8);
    }
    ISSUE_TILE(0);                           // group 0 = Q + tile0
    if (1 < nkt) ISSUE_TILE(1); else CP_COMMIT();
    if (2 < nkt) ISSUE_TILE(2); else CP_COMMIT();

    float o[8][4];
#pragma unroll
    for (int n = 0; n < 8; n++)
#pragma unroll
        for (int q = 0; q < 4; q++) o[n][q] = 0.f;
    float m0 = -1e30f, m1 = -1e30f, l0 = 0.f, l1 = 0.f;
    uint32_t aqh[4][4];

    const int r0g = qt * 128 + w * 16 + (lane >> 2);

    for (int kt = 0; kt < nkt; kt++) {
        CP_WAIT(2);                          // oldest pending (tile kt) resident
        __syncthreads();                     // single CTA barrier per tile
        if (kt + 3 < nkt) ISSUE_TILE(kt + 3); else CP_COMMIT();

        if (kt == 0) {
#pragma unroll
            for (int kc = 0; kc < 4; kc++)
                ldsm_x4(aqh[kc], QH + SWZ((w * 16 + frow) * 128 + (kc * 16 + fcol) * 2));
        }

        uint32_t st = sb + 16384 + (kt & (ASTAGES - 1)) * 16384;
        uint32_t KHs = st, VHs = st + 8192;

        // ---- S = Qh . Kh   (S is in base-2 units: q pre-scaled by log2e/8)
        float s[8][4];
#pragma unroll
        for (int n = 0; n < 8; n++)
#pragma unroll
            for (int q = 0; q < 4; q++) s[n][q] = 0.f;

#pragma unroll
        for (int kc = 0; kc < 4; kc++) {
#pragma unroll
            for (int kg = 0; kg < 4; kg++) {
                uint32_t bk[4];
                ldsm_x4(bk, KHs + SWZ((kg * 16 + frow) * 128 + (kc * 16 + fcol) * 2));
                mma16816(s[2 * kg],     aqh[kc], bk[0], bk[2]);
                mma16816(s[2 * kg + 1], aqh[kc], bk[1], bk[3]);
            }
        }

        // ---- causal mask
        const int kbase = kt * 64;
        if (kbase + 63 > qt * 128 + w * 16) {
#pragma unroll
            for (int n = 0; n < 8; n++) {
                int c = kbase + n * 8 + ((lane & 3) << 1);
                if (c     > r0g)     s[n][0] = -1e30f;
                if (c + 1 > r0g)     s[n][1] = -1e30f;
                if (c     > r0g + 8) s[n][2] = -1e30f;
                if (c + 1 > r0g + 8) s[n][3] = -1e30f;
            }
        }

        // ---- online softmax (base 2, MUFU ex2)
        float tm0 = -1e30f, tm1 = -1e30f;
#pragma unroll
        for (int n = 0; n < 8; n++) {
            tm0 = fmaxf(tm0, fmaxf(s[n][0], s[n][1]));
            tm1 = fmaxf(tm1, fmaxf(s[n][2], s[n][3]));
        }
        tm0 = fmaxf(tm0, __shfl_xor_sync(0xffffffffu, tm0, 1));
        tm0 = fmaxf(tm0, __shfl_xor_sync(0xffffffffu, tm0, 2));
        tm1 = fmaxf(tm1, __shfl_xor_sync(0xffffffffu, tm1, 1));
        tm1 = fmaxf(tm1, __shfl_xor_sync(0xffffffffu, tm1, 2));
        float mn0 = fmaxf(m0, tm0), mn1 = fmaxf(m1, tm1);
        float al0 = ex2(m0 - mn0), al1 = ex2(m1 - mn1);
        m0 = mn0; m1 = mn1;
        float ps0 = 0.f, ps1 = 0.f;
#pragma unroll
        for (int n = 0; n < 8; n++) {
            s[n][0] = ex2(s[n][0] - m0);
            s[n][1] = ex2(s[n][1] - m0);
            s[n][2] = ex2(s[n][2] - m1);
            s[n][3] = ex2(s[n][3] - m1);
            ps0 += s[n][0] + s[n][1];
            ps1 += s[n][2] + s[n][3];
        }
        l0 = l0 * al0 + ps0;
        l1 = l1 * al1 + ps1;
#pragma unroll
        for (int n = 0; n < 8; n++) {
            o[n][0] *= al0; o[n][1] *= al0;
            o[n][2] *= al1; o[n][3] *= al1;
        }

        // ---- O += Ph . Vh  (single fp16 pass)
#pragma unroll
        for (int kg = 0; kg < 4; kg++) {
            uint32_t aph[4];
            aph[0] = pack_h2(s[2 * kg][0],     s[2 * kg][1]);
            aph[1] = pack_h2(s[2 * kg][2],     s[2 * kg][3]);
            aph[2] = pack_h2(s[2 * kg + 1][0], s[2 * kg + 1][1]);
            aph[3] = pack_h2(s[2 * kg + 1][2], s[2 * kg + 1][3]);
#pragma unroll
            for (int dg = 0; dg < 4; dg++) {
                uint32_t bv[4];
                uint32_t so = SWZ((kg * 16 + frow) * 128 + (dg * 16 + fcol) * 2);
                ldsm_x4_t(bv, VHs + so);
                mma16816(o[2 * dg],     aph, bv[0], bv[1]);
                mma16816(o[2 * dg + 1], aph, bv[2], bv[3]);
            }
        }
    }
#undef ISSUE_TILE

    // ---- epilogue: write fp16 att rows
    l0 += __shfl_xor_sync(0xffffffffu, l0, 1);
    l0 += __shfl_xor_sync(0xffffffffu, l0, 2);
    l1 += __shfl_xor_sync(0xffffffffu, l1, 1);
    l1 += __shfl_xor_sync(0xffffffffu, l1, 2);
    float inv0 = 1.0f / l0, inv1 = 1.0f / l1;

    size_t row0 = (size_t)(b * Ln + qt * 128 + w * 16 + (lane >> 2));
#pragma unroll
    for (int n = 0; n < 8; n++) {
        int col = h * 64 + n * 8 + ((lane & 3) << 1);
#pragma unroll
        for (int half = 0; half < 2; half++) {
            float v0 = o[n][2 * half]     * (half ? inv1 : inv0);
            float v1 = o[n][2 * half + 1] * (half ? inv1 : inv0);
            *(__half2*)(g_atth + (row0 + half * 8) * 1024 + col) =
                __floats2half2_rn(v0, v1);
        }
    }
}

// ---------------- launch ----------------------------------------------------
extern "C" void kernel_launch(void* const* d_in, const int* in_sizes, int n_in,
                              void* d_out, int out_size)
{
    const float* x  = (const float*)d_in[0];
    const float* wq = (const float*)d_in[1];
    const float* wk = (const float*)d_in[2];
    const float* wv = (const float*)d_in[3];
    const float* wo = (const float*)d_in[4];
    const float* fc = (const float*)d_in[5];
    const float* fs = (const float*)d_in[6];
    // d_in[7] = mask: all-true by construction; causal mask applied exactly.
    float* out = (float*)d_out;
    (void)in_sizes; (void)n_in; (void)out_size;

    __half *xh, *atth, *wqkvs, *wos;
    cudaGetSymbolAddress((void**)&xh,    g_xh);
    cudaGetSymbolAddress((void**)&atth,  g_atth);
    cudaGetSymbolAddress((void**)&wqkvs, g_wqkvs);
    cudaGetSymbolAddress((void**)&wos,   g_wos);

    cudaFuncSetAttribute(gemm_fp16, cudaFuncAttributeMaxDynamicSharedMemorySize, GEMM_SMEM);
    cudaFuncSetAttribute(attn_mma, cudaFuncAttributeMaxDynamicSharedMemorySize, ATT_SMEM);

    // fp16 operand prep (one launch)
    cvt_all<<<(NCVT + 255) / 256, 256>>>(x, wq, wk, wv, wo);

    // fused QKV projection + RoPE + scatter (mode 1)
    gemm_fp16<<<dim3(QKVW / 128, 64), 256, GEMM_SMEM>>>(xh, wqkvs, nullptr, 0, fc, fs, 1);

    // causal GQA attention
    attn_mma<<<dim3(Ln / 128, Hn, Bn), 256, ATT_SMEM>>>();

    // output projection (mode 0)
    gemm_fp16<<<dim3(1024 / 128, 64), 256, GEMM_SMEM>>>(atth, wos, out, 1024, fc, fs, 0);
}

// round 15
// speedup vs baseline: 1.0857x; 1.0023x over previous
#include <cuda_runtime.h>
#include <cuda_fp16.h>
#include <stdint.h>

#define Bn  4
#define Ln  2048
#define Dn  1024
#define Hn  16
#define KVn 4
#define HDn 64
#define NROWS (Bn*Ln)          // 8192
#define QKVW  1536             // 1024 + 256 + 256
#define LOG2E 1.44269504088896341f

// ---------------- scratch (device globals; no allocations allowed) ----------
__device__ __half g_xh   [(size_t)NROWS*1024];   // x fp16 [8192][1024]
__device__ __half g_atth [(size_t)NROWS*1024];   // att fp16 [8192][1024]
__device__ __half g_wqkvs[(size_t)QKVW*1024];    // [wq|wk|wv]^T fp16 [1536][1024]
__device__ __half g_wos  [(size_t)1024*1024];    // wo^T fp16 [1024][1024]

// attention operands, fp16, head-major (q pre-scaled by 0.125*log2e)
__device__ __half g_qh[(size_t)Bn*Hn*Ln*HDn];
__device__ __half g_kh[(size_t)Bn*KVn*Ln*HDn];
__device__ __half g_vh[(size_t)Bn*KVn*Ln*HDn];

// ---------------- PTX helpers ----------------------------------------------
__device__ __forceinline__ uint32_t smem_u32(const void* p) {
    uint32_t a;
    asm("{ .reg .u64 t; cvta.to.shared.u64 t, %1; cvt.u32.u64 %0, t; }"
        : "=r"(a) : "l"(p));
    return a;
}
#define SWZ(x) ((x) ^ (((x) >> 3) & 0x70))

__device__ __forceinline__ void cp_async16(uint32_t s, const void* g) {
    asm volatile("cp.async.cg.shared.global [%0], [%1], 16;" :: "r"(s), "l"(g));
}
#define CP_COMMIT() asm volatile("cp.async.commit_group;" ::: "memory")
#define CP_WAIT(n)  asm volatile("cp.async.wait_group %0;" :: "n"(n) : "memory")

__device__ __forceinline__ void ldsm_x4(uint32_t* r, uint32_t addr) {
    asm volatile("ldmatrix.sync.aligned.m8n8.x4.shared.b16 {%0,%1,%2,%3}, [%4];"
        : "=r"(r[0]), "=r"(r[1]), "=r"(r[2]), "=r"(r[3]) : "r"(addr));
}
__device__ __forceinline__ void ldsm_x4_t(uint32_t* r, uint32_t addr) {
    asm volatile("ldmatrix.sync.aligned.m8n8.x4.trans.shared.b16 {%0,%1,%2,%3}, [%4];"
        : "=r"(r[0]), "=r"(r[1]), "=r"(r[2]), "=r"(r[3]) : "r"(addr));
}

__device__ __forceinline__ void mma16816(float* c, const uint32_t* a,
                                         uint32_t b0, uint32_t b1) {
    asm volatile(
        "mma.sync.aligned.m16n8k16.row.col.f32.f16.f16.f32 "
        "{%0,%1,%2,%3}, {%4,%5,%6,%7}, {%8,%9}, {%0,%1,%2,%3};"
        : "+f"(c[0]), "+f"(c[1]), "+f"(c[2]), "+f"(c[3])
        : "r"(a[0]), "r"(a[1]), "r"(a[2]), "r"(a[3]), "r"(b0), "r"(b1));
}

__device__ __forceinline__ uint32_t pack_h2(float lo, float hi) {
    __half2 t = __floats2half2_rn(lo, hi);
    return *(uint32_t*)&t;
}

__device__ __forceinline__ float ex2(float x) {       // force MUFU ex2.approx
    float r;
    asm("ex2.approx.ftz.f32 %0, %1;" : "=f"(r) : "f"(x));
    return r;
}

// ---------------- fp32 -> fp16 conversions ----------------------------------
#define NXA (NROWS * 512)                   // x pairs

__global__ void cvt_x(const float* __restrict__ x)
{
    int i = blockIdx.x * 256 + threadIdx.x;
    float2 v = *(const float2*)(x + (size_t)i * 2);
    *(__half2*)(g_xh + (size_t)i * 2) = __floats2half2_rn(v.x, v.y);
}

// weight transpose+cast via 32x32 smem tiles (coalesced both sides)
// z: 0=wq, 1=wk, 2=wv (into g_wqkvs rows 0/1024/1280), 3=wo (into g_wos)
__global__ void cvt_wt(const float* __restrict__ wq, const float* __restrict__ wk,
                       const float* __restrict__ wv, const float* __restrict__ wo)
{
    __shared__ float tile[32][33];
    const int z = blockIdx.z;
    const float* src;
    __half* dst;
    int N, row0;
    if (z == 0)      { src = wq; N = 1024; row0 = 0;    dst = g_wqkvs; }
    else if (z == 1) { src = wk; N = 256;  row0 = 1024; dst = g_wqkvs; }
    else if (z == 2) { src = wv; N = 256;  row0 = 1280; dst = g_wqkvs; }
    else             { src = wo; N = 1024; row0 = 0;    dst = g_wos;   }
    int n0 = blockIdx.x * 32, k0 = blockIdx.y * 32;
    if (n0 >= N) return;
    int tx = threadIdx.x, ty = threadIdx.y;           // 32 x 8
#pragma unroll
    for (int i = 0; i < 4; i++)
        tile[ty * 4 + i][tx] = src[(size_t)(k0 + ty * 4 + i) * N + n0 + tx];
    __syncthreads();
#pragma unroll
    for (int i = 0; i < 4; i++)
        dst[(size_t)(row0 + n0 + ty * 4 + i) * 1024 + k0 + tx] =
            __float2half_rn(tile[tx][ty * 4 + i]);
}

// ---------------- HMMA fp16 GEMM: C[128x128] tiles, 8 warps (64x32 each) ----
// 2 CTAs/SM.  mode 0: fp32 C store (WO).  mode 1: RoPE + scatter (QKV).
#define GSTAGES 3
#define NCHUNK 16                    // 1024 / 64
#define STAGE_BYTES 32768            // A 16KB + B 16KB
#define GEMM_SMEM (GSTAGES * STAGE_BYTES)

__global__ __launch_bounds__(256, 2) void gemm_fp16(
    const __half* __restrict__ A, const __half* __restrict__ Bm,
    float* __restrict__ C, int ldc,
    const float* __restrict__ fc, const float* __restrict__ fs, int mode)
{
    extern __shared__ char smraw[];
    uint32_t stg = smem_u32(smraw);
    const int tid  = threadIdx.x;
    const int lane = tid & 31;
    const int w    = tid >> 5;
    const int wm   = w & 1;          // 2 warps along M (64 rows each)
    const int wn   = w >> 1;         // 4 warps along N (32 cols each)
    const int m0 = blockIdx.y * 128, n0 = blockIdx.x * 128;

    const int fr  = lane & 7;
    const int fmi = lane >> 3;
    const int frow = ((fmi & 1) << 3) + fr;
    const int fcol = (fmi >> 1) << 3;

    const __half* Ag0 = A  + (size_t)m0 * 1024;
    const __half* Bg0 = Bm + (size_t)n0 * 1024;

#define ISSUE_LOADS(c, slot) do {                                             \
        uint32_t As_ = stg + (slot) * STAGE_BYTES;                            \
        uint32_t Bs_ = As_ + 16384;                                           \
        const __half* Ag = Ag0 + (c) * 64;                                    \
        const __half* Bg = Bg0 + (c) * 64;                                    \
        _Pragma("unroll")                                                     \
        for (int j_ = 0; j_ < 4; j_++) {                                      \
            int op_ = j_ * 256 + tid;                                         \
            int row_ = op_ >> 3, cb_ = op_ & 7;                               \
            uint32_t so_ = SWZ(row_ * 128 + cb_ * 16);                        \
            cp_async16(As_ + so_, Ag + (size_t)row_ * 1024 + cb_ * 8);        \
            cp_async16(Bs_ + so_, Bg + (size_t)row_ * 1024 + cb_ * 8);        \
        }                                                                     \
        CP_COMMIT();                                                          \
    } while (0)

    ISSUE_LOADS(0, 0);
    ISSUE_LOADS(1, 1);

    float acc[4][4][4];
#pragma unroll
    for (int i = 0; i < 4; i++)
#pragma unroll
        for (int j = 0; j < 4; j++)
#pragma unroll
            for (int q = 0; q < 4; q++) acc[i][j][q] = 0.f;

    int slot = 0, nslot = 2;
    for (int c = 0; c < NCHUNK; c++) {
        CP_WAIT(1);
        __syncthreads();
        if (c + 2 < NCHUNK) ISSUE_LOADS(c + 2, nslot); else CP_COMMIT();

        uint32_t As = stg + slot * STAGE_BYTES;
        uint32_t Bs = As + 16384;
#pragma unroll
        for (int ks = 0; ks < 4; ks++) {
            uint32_t a[4][4], bfr[2][4];
#pragma unroll
            for (int mt = 0; mt < 4; mt++) {
                int row = wm * 64 + mt * 16 + frow;
                ldsm_x4(a[mt], As + SWZ(row * 128 + (ks * 16 + fcol) * 2));
            }
#pragma unroll
            for (int nt = 0; nt < 2; nt++) {
                int row = wn * 32 + nt * 16 + frow;
                ldsm_x4(bfr[nt], Bs + SWZ(row * 128 + (ks * 16 + fcol) * 2));
            }
#pragma unroll
            for (int mt = 0; mt < 4; mt++)
#pragma unroll
                for (int nj = 0; nj < 4; nj++)
                    mma16816(acc[mt][nj], a[mt],
                             bfr[nj >> 1][nj & 1], bfr[nj >> 1][(nj & 1) + 2]);
        }
        slot  = (slot  == GSTAGES - 1) ? 0 : slot + 1;
        nslot = (nslot == GSTAGES - 1) ? 0 : nslot + 1;
    }
#undef ISSUE_LOADS

    if (mode == 0) {
        // plain fp32 store (output projection)
#pragma unroll
        for (int mt = 0; mt < 4; mt++) {
            int row = m0 + wm * 64 + mt * 16 + (lane >> 2);
#pragma unroll
            for (int nj = 0; nj < 4; nj++) {
                int col = n0 + wn * 32 + nj * 8 + ((lane & 3) << 1);
                float2 v0 = {acc[mt][nj][0], acc[mt][nj][1]};
                float2 v1 = {acc[mt][nj][2], acc[mt][nj][3]};
                *(float2*)(C + (size_t)row * ldc + col)       = v0;
                *(float2*)(C + (size_t)(row + 8) * ldc + col) = v1;
            }
        }
    } else {
        // fused RoPE + fp16 scatter (QKV projection); q pre-scaled by log2e/8
#pragma unroll
        for (int mt = 0; mt < 4; mt++) {
            int row = m0 + wm * 64 + mt * 16 + (lane >> 2);
#pragma unroll
            for (int nj = 0; nj < 4; nj++) {
                int col = n0 + wn * 32 + nj * 8 + ((lane & 3) << 1);
#pragma unroll
                for (int half = 0; half < 2; half++) {
                    int r = row + half * 8;
                    float v0 = acc[mt][nj][2 * half];
                    float v1 = acc[mt][nj][2 * half + 1];
                    int bb = r >> 11, l = r & (Ln - 1);
                    int d = col & 63, ii = d >> 1;
                    if (col < 1024) {
                        int h = col >> 6;
                        float cc = fc[l * 32 + ii], ss = fs[l * 32 + ii];
                        size_t ob = ((size_t)(bb * Hn + h) * Ln + l) * HDn + d;
                        const float qs = 0.125f * LOG2E;
                        *(__half2*)(g_qh + ob) = __floats2half2_rn(
                            (v0 * cc - v1 * ss) * qs, (v0 * ss + v1 * cc) * qs);
                    } else if (col < 1280) {
                        int kv = (col - 1024) >> 6;
                        float cc = fc[l * 32 + ii], ss = fs[l * 32 + ii];
                        size_t ob = ((size_t)(bb * KVn + kv) * Ln + l) * HDn + d;
                        *(__half2*)(g_kh + ob) =
                            __floats2half2_rn(v0 * cc - v1 * ss, v0 * ss + v1 * cc);
                    } else {
                        int kv = (col - 1280) >> 6;
                        size_t ob = ((size_t)(bb * KVn + kv) * Ln + l) * HDn + d;
                        *(__half2*)(g_vh + ob) = __floats2half2_rn(v0, v1);
                    }
                }
            }
        }
    }
}

// ---------------- HMMA causal flash attention, BM=128 -----------------------
// 128-key super-tiles (K 16KB + V 16KB per stage), 3-stage ring, ONE
// CP_WAIT+sync per 128 keys; two 64-key softmax/PV sub-tiles inside.
#define ASTAGES 3
#define ATT_SMEM (16384 + ASTAGES * 32768)   // 112 KB

__global__ __launch_bounds__(256, 2) void attn_mma()
{
    extern __shared__ char smraw[];
    uint32_t sb = smem_u32(smraw);
    // heavy tiles (large qt) first: better tail scheduling on triangular work
    const int qt = (gridDim.x - 1) - blockIdx.x;
    const int h = blockIdx.y, b = blockIdx.z;
    const int tid = threadIdx.x, lane = tid & 31, w = tid >> 5;
    const int frow = (((lane >> 3) & 1) << 3) + (lane & 7);
    const int fcol = (lane >> 4) << 3;

    const uint32_t QH = sb;
    const int kvh = h >> 2;
    const __half* qh_g = g_qh + ((size_t)(b * Hn + h) * Ln + qt * 128) * HDn;
    const __half* kh_g = g_kh + (size_t)(b * KVn + kvh) * Ln * HDn;
    const __half* vh_g = g_vh + (size_t)(b * KVn + kvh) * Ln * HDn;

    const int nkt2 = qt + 1;                 // 128-key tiles

#define ISSUE_TILE2(t2) do {                                                  \
        uint32_t st_ = sb + 16384 + ((t2) % ASTAGES) * 32768;                 \
        int kb_ = (t2) * 128;                                                 \
        _Pragma("unroll")                                                     \
        for (int j_ = 0; j_ < 4; j_++) {                                      \
            int op_ = j_ * 256 + tid;                                         \
            int row_ = op_ >> 3, ch_ = op_ & 7;                               \
            uint32_t so_ = SWZ(row_ * 128 + ch_ * 16);                        \
            size_t gs_ = (size_t)(kb_ + row_) * HDn + ch_ * 8;                \
            cp_async16(st_ + so_,         kh_g + gs_);                        \
            cp_async16(st_ + 16384 + so_, vh_g + gs_);                        \
        }                                                                     \
        CP_COMMIT();                                                          \
    } while (0)

    // prologue: Q folded into group 0 with tile 0; tile 1 (or empty) = group 1
#pragma unroll
    for (int j = 0; j < 4; j++) {
        int op = j * 256 + tid;
        int row = op >> 3, ch = op & 7;
        cp_async16(QH + SWZ(row * 128 + ch * 16), qh_g + (size_t)row * HDn + ch * 8);
    }
    ISSUE_TILE2(0);
    if (1 < nkt2) ISSUE_TILE2(1); else CP_COMMIT();

    float o[8][4];
#pragma unroll
    for (int n = 0; n < 8; n++)
#pragma unroll
        for (int q = 0; q < 4; q++) o[n][q] = 0.f;
    float m0 = -1e30f, m1 = -1e30f, l0 = 0.f, l1 = 0.f;
    uint32_t aqh[4][4];

    const int r0g = qt * 128 + w * 16 + (lane >> 2);

    for (int t2 = 0; t2 < nkt2; t2++) {
        CP_WAIT(1);                          // tile t2 resident (never newest)
        __syncthreads();                     // single CTA barrier per 128 keys
        if (t2 + 2 < nkt2) ISSUE_TILE2(t2 + 2); else CP_COMMIT();

        if (t2 == 0) {
#pragma unroll
            for (int kc = 0; kc < 4; kc++)
                ldsm_x4(aqh[kc], QH + SWZ((w * 16 + frow) * 128 + (kc * 16 + fcol) * 2));
        }

        uint32_t st = sb + 16384 + (t2 % ASTAGES) * 32768;

#pragma unroll
        for (int sub = 0; sub < 2; sub++) {
            uint32_t KHs = st + sub * 8192;
            uint32_t VHs = st + 16384 + sub * 8192;

            // ---- S = Qh . Kh   (base-2 units: q pre-scaled by log2e/8)
            float s[8][4];
#pragma unroll
            for (int n = 0; n < 8; n++)
#pragma unroll
                for (int q = 0; q < 4; q++) s[n][q] = 0.f;

#pragma unroll
            for (int kc = 0; kc < 4; kc++) {
#pragma unroll
                for (int kg = 0; kg < 4; kg++) {
                    uint32_t bk[4];
                    ldsm_x4(bk, KHs + SWZ((kg * 16 + frow) * 128 + (kc * 16 + fcol) * 2));
                    mma16816(s[2 * kg],     aqh[kc], bk[0], bk[2]);
                    mma16816(s[2 * kg + 1], aqh[kc], bk[1], bk[3]);
                }
            }

            // ---- causal mask
            const int kbase = t2 * 128 + sub * 64;
            if (kbase + 63 > qt * 128 + w * 16) {
#pragma unroll
                for (int n = 0; n < 8; n++) {
                    int c = kbase + n * 8 + ((lane & 3) << 1);
                    if (c     > r0g)     s[n][0] = -1e30f;
                    if (c + 1 > r0g)     s[n][1] = -1e30f;
                    if (c     > r0g + 8) s[n][2] = -1e30f;
                    if (c + 1 > r0g + 8) s[n][3] = -1e30f;
                }
            }

            // ---- online softmax (base 2, MUFU ex2)
            float tm0 = -1e30f, tm1 = -1e30f;
#pragma unroll
            for (int n = 0; n < 8; n++) {
                tm0 = fmaxf(tm0, fmaxf(s[n][0], s[n][1]));
                tm1 = fmaxf(tm1, fmaxf(s[n][2], s[n][3]));
            }
            tm0 = fmaxf(tm0, __shfl_xor_sync(0xffffffffu, tm0, 1));
            tm0 = fmaxf(tm0, __shfl_xor_sync(0xffffffffu, tm0, 2));
            tm1 = fmaxf(tm1, __shfl_xor_sync(0xffffffffu, tm1, 1));
            tm1 = fmaxf(tm1, __shfl_xor_sync(0xffffffffu, tm1, 2));
            float mn0 = fmaxf(m0, tm0), mn1 = fmaxf(m1, tm1);
            float al0 = ex2(m0 - mn0), al1 = ex2(m1 - mn1);
            m0 = mn0; m1 = mn1;
            float ps0 = 0.f, ps1 = 0.f;
#pragma unroll
            for (int n = 0; n < 8; n++) {
                s[n][0] = ex2(s[n][0] - m0);
                s[n][1] = ex2(s[n][1] - m0);
                s[n][2] = ex2(s[n][2] - m1);
                s[n][3] = ex2(s[n][3] - m1);
                ps0 += s[n][0] + s[n][1];
                ps1 += s[n][2] + s[n][3];
            }
            l0 = l0 * al0 + ps0;
            l1 = l1 * al1 + ps1;
#pragma unroll
            for (int n = 0; n < 8; n++) {
                o[n][0] *= al0; o[n][1] *= al0;
                o[n][2] *= al1; o[n][3] *= al1;
            }

            // ---- O += Ph . Vh  (single fp16 pass)
#pragma unroll
            for (int kg = 0; kg < 4; kg++) {
                uint32_t aph[4];
                aph[0] = pack_h2(s[2 * kg][0],     s[2 * kg][1]);
                aph[1] = pack_h2(s[2 * kg][2],     s[2 * kg][3]);
                aph[2] = pack_h2(s[2 * kg + 1][0], s[2 * kg + 1][1]);
                aph[3] = pack_h2(s[2 * kg + 1][2], s[2 * kg + 1][3]);
#pragma unroll
                for (int dg = 0; dg < 4; dg++) {
                    uint32_t bv[4];
                    uint32_t so = SWZ((kg * 16 + frow) * 128 + (dg * 16 + fcol) * 2);
                    ldsm_x4_t(bv, VHs + so);
                    mma16816(o[2 * dg],     aph, bv[0], bv[1]);
                    mma16816(o[2 * dg + 1], aph, bv[2], bv[3]);
                }
            }
        }
    }
#undef ISSUE_TILE2

    // ---- epilogue: write fp16 att rows
    l0 += __shfl_xor_sync(0xffffffffu, l0, 1);
    l0 += __shfl_xor_sync(0xffffffffu, l0, 2);
    l1 += __shfl_xor_sync(0xffffffffu, l1, 1);
    l1 += __shfl_xor_sync(0xffffffffu, l1, 2);
    float inv0 = 1.0f / l0, inv1 = 1.0f / l1;

    size_t row0 = (size_t)(b * Ln + qt * 128 + w * 16 + (lane >> 2));
#pragma unroll
    for (int n = 0; n < 8; n++) {
        int col = h * 64 + n * 8 + ((lane & 3) << 1);
#pragma unroll
        for (int half = 0; half < 2; half++) {
            float v0 = o[n][2 * half]     * (half ? inv1 : inv0);
            float v1 = o[n][2 * half + 1] * (half ? inv1 : inv0);
            *(__half2*)(g_atth + (row0 + half * 8) * 1024 + col) =
                __floats2half2_rn(v0, v1);
        }
    }
}

// ---------------- launch ----------------------------------------------------
extern "C" void kernel_launch(void* const* d_in, const int* in_sizes, int n_in,
                              void* d_out, int out_size)
{
    const float* x  = (const float*)d_in[0];
    const float* wq = (const float*)d_in[1];
    const float* wk = (const float*)d_in[2];
    const float* wv = (const float*)d_in[3];
    const float* wo = (const float*)d_in[4];
    const float* fc = (const float*)d_in[5];
    const float* fs = (const float*)d_in[6];
    // d_in[7] = mask: all-true by construction; causal mask applied exactly.
    float* out = (float*)d_out;
    (void)in_sizes; (void)n_in; (void)out_size;

    __half *xh, *atth, *wqkvs, *wos;
    cudaGetSymbolAddress((void**)&xh,    g_xh);
    cudaGetSymbolAddress((void**)&atth,  g_atth);
    cudaGetSymbolAddress((void**)&wqkvs, g_wqkvs);
    cudaGetSymbolAddress((void**)&wos,   g_wos);

    cudaFuncSetAttribute(gemm_fp16, cudaFuncAttributeMaxDynamicSharedMemorySize, GEMM_SMEM);
    cudaFuncSetAttribute(attn_mma, cudaFuncAttributeMaxDynamicSharedMemorySize, ATT_SMEM);

    // fp16 operand prep: x straight cast + tiled weight transpose
    cvt_x<<<NXA / 256, 256>>>(x);
    cvt_wt<<<dim3(32, 32, 4), dim3(32, 8)>>>(wq, wk, wv, wo);

    // fused QKV projection + RoPE + scatter (mode 1)
    gemm_fp16<<<dim3(QKVW / 128, 64), 256, GEMM_SMEM>>>(xh, wqkvs, nullptr, 0, fc, fs, 1);

    // causal GQA attention
    attn_mma<<<dim3(Ln / 128, Hn, Bn), 256, ATT_SMEM>>>();

    // output projection (mode 0)
    gemm_fp16<<<dim3(1024 / 128, 64), 256, GEMM_SMEM>>>(atth, wos, out, 1024, fc, fs, 0);
}

// round 16
// speedup vs baseline: 1.1038x; 1.0167x over previous
#include <cuda_runtime.h>
#include <cuda_fp16.h>
#include <stdint.h>

#define Bn  4
#define Ln  2048
#define Dn  1024
#define Hn  16
#define KVn 4
#define HDn 64
#define NROWS (Bn*Ln)          // 8192
#define QKVW  1536             // 1024 + 256 + 256
#define LOG2E 1.44269504088896341f
#define ONES_H2 0x3C003C00u    // half2(1.0, 1.0)

// ---------------- scratch (device globals; no allocations allowed) ----------
__device__ __half g_xh   [(size_t)NROWS*1024];   // x fp16 [8192][1024]
__device__ __half g_atth [(size_t)NROWS*1024];   // att fp16 [8192][1024]
__device__ __half g_wqkvs[(size_t)QKVW*1024];    // [wq|wk|wv]^T fp16 [1536][1024]
__device__ __half g_wos  [(size_t)1024*1024];    // wo^T fp16 [1024][1024]

// attention operands, fp16, head-major (q pre-scaled by 0.125*log2e)
__device__ __half g_qh[(size_t)Bn*Hn*Ln*HDn];
__device__ __half g_kh[(size_t)Bn*KVn*Ln*HDn];
__device__ __half g_vh[(size_t)Bn*KVn*Ln*HDn];

// ---------------- PTX helpers ----------------------------------------------
__device__ __forceinline__ uint32_t smem_u32(const void* p) {
    uint32_t a;
    asm("{ .reg .u64 t; cvta.to.shared.u64 t, %1; cvt.u32.u64 %0, t; }"
        : "=r"(a) : "l"(p));
    return a;
}
#define SWZ(x) ((x) ^ (((x) >> 3) & 0x70))

__device__ __forceinline__ void cp_async16(uint32_t s, const void* g) {
    asm volatile("cp.async.cg.shared.global [%0], [%1], 16;" :: "r"(s), "l"(g));
}
#define CP_COMMIT() asm volatile("cp.async.commit_group;" ::: "memory")
#define CP_WAIT(n)  asm volatile("cp.async.wait_group %0;" :: "n"(n) : "memory")

__device__ __forceinline__ void ldsm_x4(uint32_t* r, uint32_t addr) {
    asm volatile("ldmatrix.sync.aligned.m8n8.x4.shared.b16 {%0,%1,%2,%3}, [%4];"
        : "=r"(r[0]), "=r"(r[1]), "=r"(r[2]), "=r"(r[3]) : "r"(addr));
}
__device__ __forceinline__ void ldsm_x4_t(uint32_t* r, uint32_t addr) {
    asm volatile("ldmatrix.sync.aligned.m8n8.x4.trans.shared.b16 {%0,%1,%2,%3}, [%4];"
        : "=r"(r[0]), "=r"(r[1]), "=r"(r[2]), "=r"(r[3]) : "r"(addr));
}

__device__ __forceinline__ void mma16816(float* c, const uint32_t* a,
                                         uint32_t b0, uint32_t b1) {
    asm volatile(
        "mma.sync.aligned.m16n8k16.row.col.f32.f16.f16.f32 "
        "{%0,%1,%2,%3}, {%4,%5,%6,%7}, {%8,%9}, {%0,%1,%2,%3};"
        : "+f"(c[0]), "+f"(c[1]), "+f"(c[2]), "+f"(c[3])
        : "r"(a[0]), "r"(a[1]), "r"(a[2]), "r"(a[3]), "r"(b0), "r"(b1));
}

__device__ __forceinline__ uint32_t pack_h2(float lo, float hi) {
    __half2 t = __floats2half2_rn(lo, hi);
    return *(uint32_t*)&t;
}

__device__ __forceinline__ float ex2(float x) {       // force MUFU ex2.approx
    float r;
    asm("ex2.approx.ftz.f32 %0, %1;" : "=f"(r) : "f"(x));
    return r;
}
__device__ __forceinline__ uint32_t ex2h2(uint32_t x) {  // half2 MUFU exp2
    uint32_t r;
    asm("ex2.approx.f16x2 %0, %1;" : "=r"(r) : "r"(x));
    return r;
}

// ---------------- fp32 -> fp16 conversions ----------------------------------
#define NXA (NROWS * 512)                   // x pairs

__global__ void cvt_x(const float* __restrict__ x)
{
    int i = blockIdx.x * 256 + threadIdx.x;
    float2 v = *(const float2*)(x + (size_t)i * 2);
    *(__half2*)(g_xh + (size_t)i * 2) = __floats2half2_rn(v.x, v.y);
}

// weight transpose+cast via 32x32 smem tiles (coalesced both sides)
__global__ void cvt_wt(const float* __restrict__ wq, const float* __restrict__ wk,
                       const float* __restrict__ wv, const float* __restrict__ wo)
{
    __shared__ float tile[32][33];
    const int z = blockIdx.z;
    const float* src;
    __half* dst;
    int N, row0;
    if (z == 0)      { src = wq; N = 1024; row0 = 0;    dst = g_wqkvs; }
    else if (z == 1) { src = wk; N = 256;  row0 = 1024; dst = g_wqkvs; }
    else if (z == 2) { src = wv; N = 256;  row0 = 1280; dst = g_wqkvs; }
    else             { src = wo; N = 1024; row0 = 0;    dst = g_wos;   }
    int n0 = blockIdx.x * 32, k0 = blockIdx.y * 32;
    if (n0 >= N) return;
    int tx = threadIdx.x, ty = threadIdx.y;           // 32 x 8
#pragma unroll
    for (int i = 0; i < 4; i++)
        tile[ty * 4 + i][tx] = src[(size_t)(k0 + ty * 4 + i) * N + n0 + tx];
    __syncthreads();
#pragma unroll
    for (int i = 0; i < 4; i++)
        dst[(size_t)(row0 + n0 + ty * 4 + i) * 1024 + k0 + tx] =
            __float2half_rn(tile[tx][ty * 4 + i]);
}

// ---------------- HMMA fp16 GEMM: C[128x128] tiles, 8 warps (64x32 each) ----
#define GSTAGES 3
#define NCHUNK 16                    // 1024 / 64
#define STAGE_BYTES 32768            // A 16KB + B 16KB
#define GEMM_SMEM (GSTAGES * STAGE_BYTES)

__global__ __launch_bounds__(256, 2) void gemm_fp16(
    const __half* __restrict__ A, const __half* __restrict__ Bm,
    float* __restrict__ C, int ldc,
    const float* __restrict__ fc, const float* __restrict__ fs, int mode)
{
    extern __shared__ char smraw[];
    uint32_t stg = smem_u32(smraw);
    const int tid  = threadIdx.x;
    const int lane = tid & 31;
    const int w    = tid >> 5;
    const int wm   = w & 1;          // 2 warps along M (64 rows each)
    const int wn   = w >> 1;         // 4 warps along N (32 cols each)
    const int m0 = blockIdx.y * 128, n0 = blockIdx.x * 128;

    const int fr  = lane & 7;
    const int fmi = lane >> 3;
    const int frow = ((fmi & 1) << 3) + fr;
    const int fcol = (fmi >> 1) << 3;

    const __half* Ag0 = A  + (size_t)m0 * 1024;
    const __half* Bg0 = Bm + (size_t)n0 * 1024;

#define ISSUE_LOADS(c, slot) do {                                             \
        uint32_t As_ = stg + (slot) * STAGE_BYTES;                            \
        uint32_t Bs_ = As_ + 16384;                                           \
        const __half* Ag = Ag0 + (c) * 64;                                    \
        const __half* Bg = Bg0 + (c) * 64;                                    \
        _Pragma("unroll")                                                     \
        for (int j_ = 0; j_ < 4; j_++) {                                      \
            int op_ = j_ * 256 + tid;                                         \
            int row_ = op_ >> 3, cb_ = op_ & 7;                               \
            uint32_t so_ = SWZ(row_ * 128 + cb_ * 16);                        \
            cp_async16(As_ + so_, Ag + (size_t)row_ * 1024 + cb_ * 8);        \
            cp_async16(Bs_ + so_, Bg + (size_t)row_ * 1024 + cb_ * 8);        \
        }                                                                     \
        CP_COMMIT();                                                          \
    } while (0)

    ISSUE_LOADS(0, 0);
    ISSUE_LOADS(1, 1);

    float acc[4][4][4];
#pragma unroll
    for (int i = 0; i < 4; i++)
#pragma unroll
        for (int j = 0; j < 4; j++)
#pragma unroll
            for (int q = 0; q < 4; q++) acc[i][j][q] = 0.f;

    int slot = 0, nslot = 2;
    for (int c = 0; c < NCHUNK; c++) {
        CP_WAIT(1);
        __syncthreads();
        if (c + 2 < NCHUNK) ISSUE_LOADS(c + 2, nslot); else CP_COMMIT();

        uint32_t As = stg + slot * STAGE_BYTES;
        uint32_t Bs = As + 16384;
#pragma unroll
        for (int ks = 0; ks < 4; ks++) {
            uint32_t a[4][4], bfr[2][4];
#pragma unroll
            for (int mt = 0; mt < 4; mt++) {
                int row = wm * 64 + mt * 16 + frow;
                ldsm_x4(a[mt], As + SWZ(row * 128 + (ks * 16 + fcol) * 2));
            }
#pragma unroll
            for (int nt = 0; nt < 2; nt++) {
                int row = wn * 32 + nt * 16 + frow;
                ldsm_x4(bfr[nt], Bs + SWZ(row * 128 + (ks * 16 + fcol) * 2));
            }
#pragma unroll
            for (int mt = 0; mt < 4; mt++)
#pragma unroll
                for (int nj = 0; nj < 4; nj++)
                    mma16816(acc[mt][nj], a[mt],
                             bfr[nj >> 1][nj & 1], bfr[nj >> 1][(nj & 1) + 2]);
        }
        slot  = (slot  == GSTAGES - 1) ? 0 : slot + 1;
        nslot = (nslot == GSTAGES - 1) ? 0 : nslot + 1;
    }
#undef ISSUE_LOADS

    if (mode == 0) {
#pragma unroll
        for (int mt = 0; mt < 4; mt++) {
            int row = m0 + wm * 64 + mt * 16 + (lane >> 2);
#pragma unroll
            for (int nj = 0; nj < 4; nj++) {
                int col = n0 + wn * 32 + nj * 8 + ((lane & 3) << 1);
                float2 v0 = {acc[mt][nj][0], acc[mt][nj][1]};
                float2 v1 = {acc[mt][nj][2], acc[mt][nj][3]};
                *(float2*)(C + (size_t)row * ldc + col)       = v0;
                *(float2*)(C + (size_t)(row + 8) * ldc + col) = v1;
            }
        }
    } else {
#pragma unroll
        for (int mt = 0; mt < 4; mt++) {
            int row = m0 + wm * 64 + mt * 16 + (lane >> 2);
#pragma unroll
            for (int nj = 0; nj < 4; nj++) {
                int col = n0 + wn * 32 + nj * 8 + ((lane & 3) << 1);
#pragma unroll
                for (int half = 0; half < 2; half++) {
                    int r = row + half * 8;
                    float v0 = acc[mt][nj][2 * half];
                    float v1 = acc[mt][nj][2 * half + 1];
                    int bb = r >> 11, l = r & (Ln - 1);
                    int d = col & 63, ii = d >> 1;
                    if (col < 1024) {
                        int h = col >> 6;
                        float cc = fc[l * 32 + ii], ss = fs[l * 32 + ii];
                        size_t ob = ((size_t)(bb * Hn + h) * Ln + l) * HDn + d;
                        const float qs = 0.125f * LOG2E;
                        *(__half2*)(g_qh + ob) = __floats2half2_rn(
                            (v0 * cc - v1 * ss) * qs, (v0 * ss + v1 * cc) * qs);
                    } else if (col < 1280) {
                        int kv = (col - 1024) >> 6;
                        float cc = fc[l * 32 + ii], ss = fs[l * 32 + ii];
                        size_t ob = ((size_t)(bb * KVn + kv) * Ln + l) * HDn + d;
                        *(__half2*)(g_kh + ob) =
                            __floats2half2_rn(v0 * cc - v1 * ss, v0 * ss + v1 * cc);
                    } else {
                        int kv = (col - 1280) >> 6;
                        size_t ob = ((size_t)(bb * KVn + kv) * Ln + l) * HDn + d;
                        *(__half2*)(g_vh + ob) = __floats2half2_rn(v0, v1);
                    }
                }
            }
        }
    }
}

// ---------------- HMMA causal flash attention, BM=128 -----------------------
// 128-key super-tiles, 3-stage ring, one sync per 128 keys.
// Softmax: fp16x2 MUFU exp produces PV a-frags directly; row-sum l via
// an extra MMA against a ones vector (no ps FADDs, no epilogue shfl).
#define ASTAGES 3
#define ATT_SMEM (16384 + ASTAGES * 32768)   // 112 KB

__global__ __launch_bounds__(256, 2) void attn_mma()
{
    extern __shared__ char smraw[];
    uint32_t sb = smem_u32(smraw);
    const int qt = (gridDim.x - 1) - blockIdx.x;
    const int h = blockIdx.y, b = blockIdx.z;
    const int tid = threadIdx.x, lane = tid & 31, w = tid >> 5;
    const int frow = (((lane >> 3) & 1) << 3) + (lane & 7);
    const int fcol = (lane >> 4) << 3;

    const uint32_t QH = sb;
    const int kvh = h >> 2;
    const __half* qh_g = g_qh + ((size_t)(b * Hn + h) * Ln + qt * 128) * HDn;
    const __half* kh_g = g_kh + (size_t)(b * KVn + kvh) * Ln * HDn;
    const __half* vh_g = g_vh + (size_t)(b * KVn + kvh) * Ln * HDn;

    const int nkt2 = qt + 1;                 // 128-key tiles

#define ISSUE_TILE2(t2) do {                                                  \
        uint32_t st_ = sb + 16384 + ((t2) % ASTAGES) * 32768;                 \
        int kb_ = (t2) * 128;                                                 \
        _Pragma("unroll")                                                     \
        for (int j_ = 0; j_ < 4; j_++) {                                      \
            int op_ = j_ * 256 + tid;                                         \
            int row_ = op_ >> 3, ch_ = op_ & 7;                               \
            uint32_t so_ = SWZ(row_ * 128 + ch_ * 16);                        \
            size_t gs_ = (size_t)(kb_ + row_) * HDn + ch_ * 8;                \
            cp_async16(st_ + so_,         kh_g + gs_);                        \
            cp_async16(st_ + 16384 + so_, vh_g + gs_);                        \
        }                                                                     \
        CP_COMMIT();                                                          \
    } while (0)

#pragma unroll
    for (int j = 0; j < 4; j++) {
        int op = j * 256 + tid;
        int row = op >> 3, ch = op & 7;
        cp_async16(QH + SWZ(row * 128 + ch * 16), qh_g + (size_t)row * HDn + ch * 8);
    }
    ISSUE_TILE2(0);
    if (1 < nkt2) ISSUE_TILE2(1); else CP_COMMIT();

    float o[8][4];
#pragma unroll
    for (int n = 0; n < 8; n++)
#pragma unroll
        for (int q = 0; q < 4; q++) o[n][q] = 0.f;
    float l_acc[4] = {0.f, 0.f, 0.f, 0.f};
    float m0 = -1e30f, m1 = -1e30f;
    uint32_t aqh[4][4];

    const int r0g = qt * 128 + w * 16 + (lane >> 2);

    for (int t2 = 0; t2 < nkt2; t2++) {
        CP_WAIT(1);
        __syncthreads();
        if (t2 + 2 < nkt2) ISSUE_TILE2(t2 + 2); else CP_COMMIT();

        if (t2 == 0) {
#pragma unroll
            for (int kc = 0; kc < 4; kc++)
                ldsm_x4(aqh[kc], QH + SWZ((w * 16 + frow) * 128 + (kc * 16 + fcol) * 2));
        }

        uint32_t st = sb + 16384 + (t2 % ASTAGES) * 32768;

#pragma unroll
        for (int sub = 0; sub < 2; sub++) {
            uint32_t KHs = st + sub * 8192;
            uint32_t VHs = st + 16384 + sub * 8192;

            // ---- S = Qh . Kh   (base-2 units)
            float s[8][4];
#pragma unroll
            for (int n = 0; n < 8; n++)
#pragma unroll
                for (int q = 0; q < 4; q++) s[n][q] = 0.f;

#pragma unroll
            for (int kc = 0; kc < 4; kc++) {
#pragma unroll
                for (int kg = 0; kg < 4; kg++) {
                    uint32_t bk[4];
                    ldsm_x4(bk, KHs + SWZ((kg * 16 + frow) * 128 + (kc * 16 + fcol) * 2));
                    mma16816(s[2 * kg],     aqh[kc], bk[0], bk[2]);
                    mma16816(s[2 * kg + 1], aqh[kc], bk[1], bk[3]);
                }
            }

            // ---- causal mask
            const int kbase = t2 * 128 + sub * 64;
            if (kbase + 63 > qt * 128 + w * 16) {
#pragma unroll
                for (int n = 0; n < 8; n++) {
                    int c = kbase + n * 8 + ((lane & 3) << 1);
                    if (c     > r0g)     s[n][0] = -1e30f;
                    if (c + 1 > r0g)     s[n][1] = -1e30f;
                    if (c     > r0g + 8) s[n][2] = -1e30f;
                    if (c + 1 > r0g + 8) s[n][3] = -1e30f;
                }
            }

            // ---- online softmax: max reduce + rescale
            float tm0 = -1e30f, tm1 = -1e30f;
#pragma unroll
            for (int n = 0; n < 8; n++) {
                tm0 = fmaxf(tm0, fmaxf(s[n][0], s[n][1]));
                tm1 = fmaxf(tm1, fmaxf(s[n][2], s[n][3]));
            }
            tm0 = fmaxf(tm0, __shfl_xor_sync(0xffffffffu, tm0, 1));
            tm0 = fmaxf(tm0, __shfl_xor_sync(0xffffffffu, tm0, 2));
            tm1 = fmaxf(tm1, __shfl_xor_sync(0xffffffffu, tm1, 1));
            tm1 = fmaxf(tm1, __shfl_xor_sync(0xffffffffu, tm1, 2));
            float mn0 = fmaxf(m0, tm0), mn1 = fmaxf(m1, tm1);
            float al0 = ex2(m0 - mn0), al1 = ex2(m1 - mn1);
            m0 = mn0; m1 = mn1;
#pragma unroll
            for (int n = 0; n < 8; n++) {
                o[n][0] *= al0; o[n][1] *= al0;
                o[n][2] *= al1; o[n][3] *= al1;
            }
            l_acc[0] *= al0; l_acc[1] *= al0;
            l_acc[2] *= al1; l_acc[3] *= al1;

            // ---- P = exp2(S - m) in fp16x2; l += P.1 ; O += P.Vh
#pragma unroll
            for (int kg = 0; kg < 4; kg++) {
                uint32_t aph[4];
                aph[0] = ex2h2(pack_h2(s[2 * kg][0] - m0,     s[2 * kg][1] - m0));
                aph[1] = ex2h2(pack_h2(s[2 * kg][2] - m1,     s[2 * kg][3] - m1));
                aph[2] = ex2h2(pack_h2(s[2 * kg + 1][0] - m0, s[2 * kg + 1][1] - m0));
                aph[3] = ex2h2(pack_h2(s[2 * kg + 1][2] - m1, s[2 * kg + 1][3] - m1));
                mma16816(l_acc, aph, ONES_H2, ONES_H2);   // row sums
#pragma unroll
                for (int dg = 0; dg < 4; dg++) {
                    uint32_t bv[4];
                    uint32_t so = SWZ((kg * 16 + frow) * 128 + (dg * 16 + fcol) * 2);
                    ldsm_x4_t(bv, VHs + so);
                    mma16816(o[2 * dg],     aph, bv[0], bv[1]);
                    mma16816(o[2 * dg + 1], aph, bv[2], bv[3]);
                }
            }
        }
    }
#undef ISSUE_TILE2

    // ---- epilogue (l_acc holds complete row sums; no shfl needed)
    float inv0 = 1.0f / l_acc[0], inv1 = 1.0f / l_acc[2];

    size_t row0 = (size_t)(b * Ln + qt * 128 + w * 16 + (lane >> 2));
#pragma unroll
    for (int n = 0; n < 8; n++) {
        int col = h * 64 + n * 8 + ((lane & 3) << 1);
#pragma unroll
        for (int half = 0; half < 2; half++) {
            float v0 = o[n][2 * half]     * (half ? inv1 : inv0);
            float v1 = o[n][2 * half + 1] * (half ? inv1 : inv0);
            *(__half2*)(g_atth + (row0 + half * 8) * 1024 + col) =
                __floats2half2_rn(v0, v1);
        }
    }
}

// ---------------- launch ----------------------------------------------------
extern "C" void kernel_launch(void* const* d_in, const int* in_sizes, int n_in,
                              void* d_out, int out_size)
{
    const float* x  = (const float*)d_in[0];
    const float* wq = (const float*)d_in[1];
    const float* wk = (const float*)d_in[2];
    const float* wv = (const float*)d_in[3];
    const float* wo = (const float*)d_in[4];
    const float* fc = (const float*)d_in[5];
    const float* fs = (const float*)d_in[6];
    // d_in[7] = mask: all-true by construction; causal mask applied exactly.
    float* out = (float*)d_out;
    (void)in_sizes; (void)n_in; (void)out_size;

    __half *xh, *atth, *wqkvs, *wos;
    cudaGetSymbolAddress((void**)&xh,    g_xh);
    cudaGetSymbolAddress((void**)&atth,  g_atth);
    cudaGetSymbolAddress((void**)&wqkvs, g_wqkvs);
    cudaGetSymbolAddress((void**)&wos,   g_wos);

    cudaFuncSetAttribute(gemm_fp16, cudaFuncAttributeMaxDynamicSharedMemorySize, GEMM_SMEM);
    cudaFuncSetAttribute(attn_mma, cudaFuncAttributeMaxDynamicSharedMemorySize, ATT_SMEM);

    // fp16 operand prep
    cvt_x<<<NXA / 256, 256>>>(x);
    cvt_wt<<<dim3(32, 32, 4), dim3(32, 8)>>>(wq, wk, wv, wo);

    // fused QKV projection + RoPE + scatter (mode 1)
    gemm_fp16<<<dim3(QKVW / 128, 64), 256, GEMM_SMEM>>>(xh, wqkvs, nullptr, 0, fc, fs, 1);

    // causal GQA attention
    attn_mma<<<dim3(Ln / 128, Hn, Bn), 256, ATT_SMEM>>>();

    // output projection (mode 0)
    gemm_fp16<<<dim3(1024 / 128, 64), 256, GEMM_SMEM>>>(atth, wos, out, 1024, fc, fs, 0);
}

// round 17
// speedup vs baseline: 1.1384x; 1.0313x over previous
#include <cuda_runtime.h>
#include <cuda_fp16.h>
#include <stdint.h>

#define Bn  4
#define Ln  2048
#define Dn  1024
#define Hn  16
#define KVn 4
#define HDn 64
#define NROWS (Bn*Ln)          // 8192
#define QKVW  1536             // 1024 + 256 + 256
#define LOG2E 1.44269504088896341f
#define ONES_H2 0x3C003C00u    // half2(1.0, 1.0)

// ---------------- scratch (device globals; no allocations allowed) ----------
__device__ __half g_xh   [(size_t)NROWS*1024];   // x fp16 [8192][1024]
__device__ __half g_atth [(size_t)NROWS*1024];   // att fp16 [8192][1024]
__device__ __half g_wqkvs[(size_t)QKVW*1024];    // [wq|wk|wv]^T fp16 [1536][1024]
__device__ __half g_wos  [(size_t)1024*1024];    // wo^T fp16 [1024][1024]

// attention operands, fp16, head-major (q pre-scaled by 0.125*log2e)
__device__ __half g_qh[(size_t)Bn*Hn*Ln*HDn];
__device__ __half g_kh[(size_t)Bn*KVn*Ln*HDn];
__device__ __half g_vh[(size_t)Bn*KVn*Ln*HDn];

// ---------------- PTX helpers ----------------------------------------------
__device__ __forceinline__ uint32_t smem_u32(const void* p) {
    uint32_t a;
    asm("{ .reg .u64 t; cvta.to.shared.u64 t, %1; cvt.u32.u64 %0, t; }"
        : "=r"(a) : "l"(p));
    return a;
}
#define SWZ(x) ((x) ^ (((x) >> 3) & 0x70))

__device__ __forceinline__ void cp_async16(uint32_t s, const void* g) {
    asm volatile("cp.async.cg.shared.global [%0], [%1], 16;" :: "r"(s), "l"(g));
}
#define CP_COMMIT() asm volatile("cp.async.commit_group;" ::: "memory")
#define CP_WAIT(n)  asm volatile("cp.async.wait_group %0;" :: "n"(n) : "memory")

__device__ __forceinline__ void ldsm_x4(uint32_t* r, uint32_t addr) {
    asm volatile("ldmatrix.sync.aligned.m8n8.x4.shared.b16 {%0,%1,%2,%3}, [%4];"
        : "=r"(r[0]), "=r"(r[1]), "=r"(r[2]), "=r"(r[3]) : "r"(addr));
}
__device__ __forceinline__ void ldsm_x4_t(uint32_t* r, uint32_t addr) {
    asm volatile("ldmatrix.sync.aligned.m8n8.x4.trans.shared.b16 {%0,%1,%2,%3}, [%4];"
        : "=r"(r[0]), "=r"(r[1]), "=r"(r[2]), "=r"(r[3]) : "r"(addr));
}

__device__ __forceinline__ void mma16816(float* c, const uint32_t* a,
                                         uint32_t b0, uint32_t b1) {
    asm volatile(
        "mma.sync.aligned.m16n8k16.row.col.f32.f16.f16.f32 "
        "{%0,%1,%2,%3}, {%4,%5,%6,%7}, {%8,%9}, {%0,%1,%2,%3};"
        : "+f"(c[0]), "+f"(c[1]), "+f"(c[2]), "+f"(c[3])
        : "r"(a[0]), "r"(a[1]), "r"(a[2]), "r"(a[3]), "r"(b0), "r"(b1));
}

__device__ __forceinline__ uint32_t pack_h2(float lo, float hi) {
    __half2 t = __floats2half2_rn(lo, hi);
    return *(uint32_t*)&t;
}

__device__ __forceinline__ float ex2(float x) {       // force MUFU ex2.approx
    float r;
    asm("ex2.approx.ftz.f32 %0, %1;" : "=f"(r) : "f"(x));
    return r;
}
__device__ __forceinline__ uint32_t ex2h2(uint32_t x) {  // half2 MUFU exp2
    uint32_t r;
    asm("ex2.approx.f16x2 %0, %1;" : "=r"(r) : "r"(x));
    return r;
}

// ---------------- fp32 -> fp16 conversions ----------------------------------
#define NXA (NROWS * 512)                   // x pairs

__global__ void cvt_x(const float* __restrict__ x)
{
    int i = blockIdx.x * 256 + threadIdx.x;
    float2 v = *(const float2*)(x + (size_t)i * 2);
    *(__half2*)(g_xh + (size_t)i * 2) = __floats2half2_rn(v.x, v.y);
}

// weight transpose+cast via 32x32 smem tiles (coalesced both sides)
__global__ void cvt_wt(const float* __restrict__ wq, const float* __restrict__ wk,
                       const float* __restrict__ wv, const float* __restrict__ wo)
{
    __shared__ float tile[32][33];
    const int z = blockIdx.z;
    const float* src;
    __half* dst;
    int N, row0;
    if (z == 0)      { src = wq; N = 1024; row0 = 0;    dst = g_wqkvs; }
    else if (z == 1) { src = wk; N = 256;  row0 = 1024; dst = g_wqkvs; }
    else if (z == 2) { src = wv; N = 256;  row0 = 1280; dst = g_wqkvs; }
    else             { src = wo; N = 1024; row0 = 0;    dst = g_wos;   }
    int n0 = blockIdx.x * 32, k0 = blockIdx.y * 32;
    if (n0 >= N) return;
    int tx = threadIdx.x, ty = threadIdx.y;           // 32 x 8
#pragma unroll
    for (int i = 0; i < 4; i++)
        tile[ty * 4 + i][tx] = src[(size_t)(k0 + ty * 4 + i) * N + n0 + tx];
    __syncthreads();
#pragma unroll
    for (int i = 0; i < 4; i++)
        dst[(size_t)(row0 + n0 + ty * 4 + i) * 1024 + k0 + tx] =
            __float2half_rn(tile[tx][ty * 4 + i]);
}

// ---------------- HMMA fp16 GEMM: C[64x128] tiles, 8 warps (32x32 each) -----
// 3 CTAs/SM (85-reg cap).  mode 0: fp32 C store (WO).  mode 1: RoPE + scatter.
#define GSTAGES 3
#define NCHUNK 16                    // 1024 / 64
#define STAGE_BYTES 24576            // A 8KB + B 16KB
#define GEMM_SMEM (GSTAGES * STAGE_BYTES)

__global__ __launch_bounds__(256, 3) void gemm_fp16(
    const __half* __restrict__ A, const __half* __restrict__ Bm,
    float* __restrict__ C, int ldc,
    const float* __restrict__ fc, const float* __restrict__ fs, int mode)
{
    extern __shared__ char smraw[];
    uint32_t stg = smem_u32(smraw);
    const int tid  = threadIdx.x;
    const int lane = tid & 31;
    const int w    = tid >> 5;
    const int wm   = w & 1;          // 2 warps along M (32 rows each)
    const int wn   = w >> 1;         // 4 warps along N (32 cols each)
    const int m0 = blockIdx.y * 64, n0 = blockIdx.x * 128;

    const int fr  = lane & 7;
    const int fmi = lane >> 3;
    const int frow = ((fmi & 1) << 3) + fr;
    const int fcol = (fmi >> 1) << 3;

    const __half* Ag0 = A  + (size_t)m0 * 1024;
    const __half* Bg0 = Bm + (size_t)n0 * 1024;

#define ISSUE_LOADS(c, slot) do {                                             \
        uint32_t As_ = stg + (slot) * STAGE_BYTES;                            \
        uint32_t Bs_ = As_ + 8192;                                            \
        const __half* Ag = Ag0 + (c) * 64;                                    \
        const __half* Bg = Bg0 + (c) * 64;                                    \
        _Pragma("unroll")                                                     \
        for (int j_ = 0; j_ < 2; j_++) {                                      \
            int op_ = j_ * 256 + tid;                                         \
            int row_ = op_ >> 3, cb_ = op_ & 7;                               \
            cp_async16(As_ + SWZ(row_ * 128 + cb_ * 16),                      \
                       Ag + (size_t)row_ * 1024 + cb_ * 8);                   \
        }                                                                     \
        _Pragma("unroll")                                                     \
        for (int j_ = 0; j_ < 4; j_++) {                                      \
            int op_ = j_ * 256 + tid;                                         \
            int row_ = op_ >> 3, cb_ = op_ & 7;                               \
            cp_async16(Bs_ + SWZ(row_ * 128 + cb_ * 16),                      \
                       Bg + (size_t)row_ * 1024 + cb_ * 8);                   \
        }                                                                     \
        CP_COMMIT();                                                          \
    } while (0)

    ISSUE_LOADS(0, 0);
    ISSUE_LOADS(1, 1);

    float acc[2][4][4];
#pragma unroll
    for (int i = 0; i < 2; i++)
#pragma unroll
        for (int j = 0; j < 4; j++)
#pragma unroll
            for (int q = 0; q < 4; q++) acc[i][j][q] = 0.f;

    int slot = 0, nslot = 2;
    for (int c = 0; c < NCHUNK; c++) {
        CP_WAIT(1);
        __syncthreads();
        if (c + 2 < NCHUNK) ISSUE_LOADS(c + 2, nslot); else CP_COMMIT();

        uint32_t As = stg + slot * STAGE_BYTES;
        uint32_t Bs = As + 8192;
#pragma unroll
        for (int ks = 0; ks < 4; ks++) {
            uint32_t a[2][4], bfr[2][4];
#pragma unroll
            for (int mt = 0; mt < 2; mt++) {
                int row = wm * 32 + mt * 16 + frow;
                ldsm_x4(a[mt], As + SWZ(row * 128 + (ks * 16 + fcol) * 2));
            }
#pragma unroll
            for (int nt = 0; nt < 2; nt++) {
                int row = wn * 32 + nt * 16 + frow;
                ldsm_x4(bfr[nt], Bs + SWZ(row * 128 + (ks * 16 + fcol) * 2));
            }
#pragma unroll
            for (int mt = 0; mt < 2; mt++)
#pragma unroll
                for (int nj = 0; nj < 4; nj++)
                    mma16816(acc[mt][nj], a[mt],
                             bfr[nj >> 1][nj & 1], bfr[nj >> 1][(nj & 1) + 2]);
        }
        slot  = (slot  == GSTAGES - 1) ? 0 : slot + 1;
        nslot = (nslot == GSTAGES - 1) ? 0 : nslot + 1;
    }
#undef ISSUE_LOADS

    if (mode == 0) {
#pragma unroll
        for (int mt = 0; mt < 2; mt++) {
            int row = m0 + wm * 32 + mt * 16 + (lane >> 2);
#pragma unroll
            for (int nj = 0; nj < 4; nj++) {
                int col = n0 + wn * 32 + nj * 8 + ((lane & 3) << 1);
                float2 v0 = {acc[mt][nj][0], acc[mt][nj][1]};
                float2 v1 = {acc[mt][nj][2], acc[mt][nj][3]};
                *(float2*)(C + (size_t)row * ldc + col)       = v0;
                *(float2*)(C + (size_t)(row + 8) * ldc + col) = v1;
            }
        }
    } else {
#pragma unroll
        for (int mt = 0; mt < 2; mt++) {
            int row = m0 + wm * 32 + mt * 16 + (lane >> 2);
#pragma unroll
            for (int nj = 0; nj < 4; nj++) {
                int col = n0 + wn * 32 + nj * 8 + ((lane & 3) << 1);
#pragma unroll
                for (int half = 0; half < 2; half++) {
                    int r = row + half * 8;
                    float v0 = acc[mt][nj][2 * half];
                    float v1 = acc[mt][nj][2 * half + 1];
                    int bb = r >> 11, l = r & (Ln - 1);
                    int d = col & 63, ii = d >> 1;
                    if (col < 1024) {
                        int h = col >> 6;
                        float cc = fc[l * 32 + ii], ss = fs[l * 32 + ii];
                        size_t ob = ((size_t)(bb * Hn + h) * Ln + l) * HDn + d;
                        const float qs = 0.125f * LOG2E;
                        *(__half2*)(g_qh + ob) = __floats2half2_rn(
                            (v0 * cc - v1 * ss) * qs, (v0 * ss + v1 * cc) * qs);
                    } else if (col < 1280) {
                        int kv = (col - 1024) >> 6;
                        float cc = fc[l * 32 + ii], ss = fs[l * 32 + ii];
                        size_t ob = ((size_t)(bb * KVn + kv) * Ln + l) * HDn + d;
                        *(__half2*)(g_kh + ob) =
                            __floats2half2_rn(v0 * cc - v1 * ss, v0 * ss + v1 * cc);
                    } else {
                        int kv = (col - 1280) >> 6;
                        size_t ob = ((size_t)(bb * KVn + kv) * Ln + l) * HDn + d;
                        *(__half2*)(g_vh + ob) = __floats2half2_rn(v0, v1);
                    }
                }
            }
        }
    }
}

// ---------------- HMMA causal flash attention, BM=128 (unchanged R16) -------
#define ASTAGES 3
#define ATT_SMEM (16384 + ASTAGES * 32768)   // 112 KB

__global__ __launch_bounds__(256, 2) void attn_mma()
{
    extern __shared__ char smraw[];
    uint32_t sb = smem_u32(smraw);
    const int qt = (gridDim.x - 1) - blockIdx.x;
    const int h = blockIdx.y, b = blockIdx.z;
    const int tid = threadIdx.x, lane = tid & 31, w = tid >> 5;
    const int frow = (((lane >> 3) & 1) << 3) + (lane & 7);
    const int fcol = (lane >> 4) << 3;

    const uint32_t QH = sb;
    const int kvh = h >> 2;
    const __half* qh_g = g_qh + ((size_t)(b * Hn + h) * Ln + qt * 128) * HDn;
    const __half* kh_g = g_kh + (size_t)(b * KVn + kvh) * Ln * HDn;
    const __half* vh_g = g_vh + (size_t)(b * KVn + kvh) * Ln * HDn;

    const int nkt2 = qt + 1;                 // 128-key tiles

#define ISSUE_TILE2(t2) do {                                                  \
        uint32_t st_ = sb + 16384 + ((t2) % ASTAGES) * 32768;                 \
        int kb_ = (t2) * 128;                                                 \
        _Pragma("unroll")                                                     \
        for (int j_ = 0; j_ < 4; j_++) {                                      \
            int op_ = j_ * 256 + tid;                                         \
            int row_ = op_ >> 3, ch_ = op_ & 7;                               \
            uint32_t so_ = SWZ(row_ * 128 + ch_ * 16);                        \
            size_t gs_ = (size_t)(kb_ + row_) * HDn + ch_ * 8;                \
            cp_async16(st_ + so_,         kh_g + gs_);                        \
            cp_async16(st_ + 16384 + so_, vh_g + gs_);                       \
        }                                                                     \
        CP_COMMIT();                                                          \
    } while (0)

#pragma unroll
    for (int j = 0; j < 4; j++) {
        int op = j * 256 + tid;
        int row = op >> 3, ch = op & 7;
        cp_async16(QH + SWZ(row * 128 + ch * 16), qh_g + (size_t)row * HDn + ch * 8);
    }
    ISSUE_TILE2(0);
    if (1 < nkt2) ISSUE_TILE2(1); else CP_COMMIT();

    float o[8][4];
#pragma unroll
    for (int n = 0; n < 8; n++)
#pragma unroll
        for (int q = 0; q < 4; q++) o[n][q] = 0.f;
    float l_acc[4] = {0.f, 0.f, 0.f, 0.f};
    float m0 = -1e30f, m1 = -1e30f;
    uint32_t aqh[4][4];

    const int r0g = qt * 128 + w * 16 + (lane >> 2);

    for (int t2 = 0; t2 < nkt2; t2++) {
        CP_WAIT(1);
        __syncthreads();
        if (t2 + 2 < nkt2) ISSUE_TILE2(t2 + 2); else CP_COMMIT();

        if (t2 == 0) {
#pragma unroll
            for (int kc = 0; kc < 4; kc++)
                ldsm_x4(aqh[kc], QH + SWZ((w * 16 + frow) * 128 + (kc * 16 + fcol) * 2));
        }

        uint32_t st = sb + 16384 + (t2 % ASTAGES) * 32768;

#pragma unroll
        for (int sub = 0; sub < 2; sub++) {
            uint32_t KHs = st + sub * 8192;
            uint32_t VHs = st + 16384 + sub * 8192;

            float s[8][4];
#pragma unroll
            for (int n = 0; n < 8; n++)
#pragma unroll
                for (int q = 0; q < 4; q++) s[n][q] = 0.f;

#pragma unroll
            for (int kc = 0; kc < 4; kc++) {
#pragma unroll
                for (int kg = 0; kg < 4; kg++) {
                    uint32_t bk[4];
                    ldsm_x4(bk, KHs + SWZ((kg * 16 + frow) * 128 + (kc * 16 + fcol) * 2));
                    mma16816(s[2 * kg],     aqh[kc], bk[0], bk[2]);
                    mma16816(s[2 * kg + 1], aqh[kc], bk[1], bk[3]);
                }
            }

            const int kbase = t2 * 128 + sub * 64;
            if (kbase + 63 > qt * 128 + w * 16) {
#pragma unroll
                for (int n = 0; n < 8; n++) {
                    int c = kbase + n * 8 + ((lane & 3) << 1);
                    if (c     > r0g)     s[n][0] = -1e30f;
                    if (c + 1 > r0g)     s[n][1] = -1e30f;
                    if (c     > r0g + 8) s[n][2] = -1e30f;
                    if (c + 1 > r0g + 8) s[n][3] = -1e30f;
                }
            }

            float tm0 = -1e30f, tm1 = -1e30f;
#pragma unroll
            for (int n = 0; n < 8; n++) {
                tm0 = fmaxf(tm0, fmaxf(s[n][0], s[n][1]));
                tm1 = fmaxf(tm1, fmaxf(s[n][2], s[n][3]));
            }
            tm0 = fmaxf(tm0, __shfl_xor_sync(0xffffffffu, tm0, 1));
            tm0 = fmaxf(tm0, __shfl_xor_sync(0xffffffffu, tm0, 2));
            tm1 = fmaxf(tm1, __shfl_xor_sync(0xffffffffu, tm1, 1));
            tm1 = fmaxf(tm1, __shfl_xor_sync(0xffffffffu, tm1, 2));
            float mn0 = fmaxf(m0, tm0), mn1 = fmaxf(m1, tm1);
            float al0 = ex2(m0 - mn0), al1 = ex2(m1 - mn1);
            m0 = mn0; m1 = mn1;
#pragma unroll
            for (int n = 0; n < 8; n++) {
                o[n][0] *= al0; o[n][1] *= al0;
                o[n][2] *= al1; o[n][3] *= al1;
            }
            l_acc[0] *= al0; l_acc[1] *= al0;
            l_acc[2] *= al1; l_acc[3] *= al1;

#pragma unroll
            for (int kg = 0; kg < 4; kg++) {
                uint32_t aph[4];
                aph[0] = ex2h2(pack_h2(s[2 * kg][0] - m0,     s[2 * kg][1] - m0));
                aph[1] = ex2h2(pack_h2(s[2 * kg][2] - m1,     s[2 * kg][3] - m1));
                aph[2] = ex2h2(pack_h2(s[2 * kg + 1][0] - m0, s[2 * kg + 1][1] - m0));
                aph[3] = ex2h2(pack_h2(s[2 * kg + 1][2] - m1, s[2 * kg + 1][3] - m1));
                mma16816(l_acc, aph, ONES_H2, ONES_H2);   // row sums
#pragma unroll
                for (int dg = 0; dg < 4; dg++) {
                    uint32_t bv[4];
                    uint32_t so = SWZ((kg * 16 + frow) * 128 + (dg * 16 + fcol) * 2);
                    ldsm_x4_t(bv, VHs + so);
                    mma16816(o[2 * dg],     aph, bv[0], bv[1]);
                    mma16816(o[2 * dg + 1], aph, bv[2], bv[3]);
                }
            }
        }
    }
#undef ISSUE_TILE2

    float inv0 = 1.0f / l_acc[0], inv1 = 1.0f / l_acc[2];

    size_t row0 = (size_t)(b * Ln + qt * 128 + w * 16 + (lane >> 2));
#pragma unroll
    for (int n = 0; n < 8; n++) {
        int col = h * 64 + n * 8 + ((lane & 3) << 1);
#pragma unroll
        for (int half = 0; half < 2; half++) {
            float v0 = o[n][2 * half]     * (half ? inv1 : inv0);
            float v1 = o[n][2 * half + 1] * (half ? inv1 : inv0);
            *(__half2*)(g_atth + (row0 + half * 8) * 1024 + col) =
                __floats2half2_rn(v0, v1);
        }
    }
}

// ---------------- launch ----------------------------------------------------
extern "C" void kernel_launch(void* const* d_in, const int* in_sizes, int n_in,
                              void* d_out, int out_size)
{
    const float* x  = (const float*)d_in[0];
    const float* wq = (const float*)d_in[1];
    const float* wk = (const float*)d_in[2];
    const float* wv = (const float*)d_in[3];
    const float* wo = (const float*)d_in[4];
    const float* fc = (const float*)d_in[5];
    const float* fs = (const float*)d_in[6];
    // d_in[7] = mask: all-true by construction; causal mask applied exactly.
    float* out = (float*)d_out;
    (void)in_sizes; (void)n_in; (void)out_size;

    __half *xh, *atth, *wqkvs, *wos;
    cudaGetSymbolAddress((void**)&xh,    g_xh);
    cudaGetSymbolAddress((void**)&atth,  g_atth);
    cudaGetSymbolAddress((void**)&wqkvs, g_wqkvs);
    cudaGetSymbolAddress((void**)&wos,   g_wos);

    cudaFuncSetAttribute(gemm_fp16, cudaFuncAttributeMaxDynamicSharedMemorySize, GEMM_SMEM);
    cudaFuncSetAttribute(attn_mma, cudaFuncAttributeMaxDynamicSharedMemorySize, ATT_SMEM);

    // fp16 operand prep
    cvt_x<<<NXA / 256, 256>>>(x);
    cvt_wt<<<dim3(32, 32, 4), dim3(32, 8)>>>(wq, wk, wv, wo);

    // fused QKV projection + RoPE + scatter (mode 1): 64x128 tiles
    gemm_fp16<<<dim3(QKVW / 128, NROWS / 64), 256, GEMM_SMEM>>>(xh, wqkvs, nullptr, 0, fc, fs, 1);

    // causal GQA attention
    attn_mma<<<dim3(Ln / 128, Hn, Bn), 256, ATT_SMEM>>>();

    // output projection (mode 0)
    gemm_fp16<<<dim3(1024 / 128, NROWS / 64), 256, GEMM_SMEM>>>(atth, wos, out, 1024, fc, fs, 0);
}